// round 1
// baseline (speedup 1.0000x reference)
#include <cuda_runtime.h>
#include <cuda_bf16.h>
#include <math.h>

// ---------------------------------------------------------------------------
// MultiModalFusionGAT: heterogeneous GAT with 4 node types and 4 edge types.
// H=8 heads, DH=16, HID=128.
//
// Key algebraic simplifications:
//  * relation transform (einsum nhd,hde->nhe) folds into projection weights
//  * segment softmax = (sum e^a * msg) / (sum e^a + eps); max-subtraction
//    cancels exactly, so a single atomic accumulation pass suffices.
// ---------------------------------------------------------------------------

#define HID 128
#define NH  8
#define DH  16

#define N_USER  20000
#define N_ITEM  50000
#define N_TASTE 50000
#define N_IMAGE 50000

// scratch layout (in floats)
#define OFF_Q_USER   0ll
#define OFF_Q_ITEM   2560000ll
#define OFF_KR_USER  8960000ll
#define OFF_VR_USER  11520000ll
#define OFF_KR_ITEM  14080000ll
#define OFF_VR_ITEM  20480000ll
#define OFF_KR_TASTE 26880000ll
#define OFF_VR_TASTE 33280000ll
#define OFF_KR_IMAGE 39680000ll
#define OFF_VR_IMAGE 46080000ll
#define OFF_NUM_ITEM 52480000ll
#define OFF_DEN_ITEM 58880000ll
#define OFF_NUM_USER 59280000ll
#define OFF_DEN_USER 61840000ll
#define OFF_GEL_ITEM 62000000ll
#define OFF_GEL_USER 68400000ll
#define OFF_WKA      70960000ll
#define OFF_WVM      71025536ll
#define OFF_BKA      71091072ll
#define OFF_BVM      71091584ll
#define SCRATCH_TOTAL 71092096ll

__device__ float g_scratch[SCRATCH_TOTAL];

// ---------------------------------------------------------------------------
// zero the accumulator region (num_item .. den_user, contiguous)
// ---------------------------------------------------------------------------
__global__ void zero_kernel(float4* __restrict__ p, int n4) {
    int i = blockIdx.x * blockDim.x + threadIdx.x;
    int stride = gridDim.x * blockDim.x;
    float4 z = make_float4(0.f, 0.f, 0.f, 0.f);
    for (; i < n4; i += stride) p[i] = z;
}

// ---------------------------------------------------------------------------
// Fold per-head relation matrix into the projection weight:
//   Wout[r][c][h*16+e] = sum_d Wsrc[tmap(r)][c][h*16+d] * rel[r][h][d][e]
//   bout[r][h*16+e]    = sum_d bsrc[tmap(r)][h*16+d]    * rel[r][h][d][e]
// ---------------------------------------------------------------------------
__global__ void fuse_rel_kernel(const float* __restrict__ Wsrc,
                                const float* __restrict__ bsrc,
                                const float* __restrict__ rel,
                                float* __restrict__ Wout,
                                float* __restrict__ bout) {
    int idx = blockIdx.x * blockDim.x + threadIdx.x;
    if (idx >= 4 * 128 * 128) return;
    int r  = idx >> 14;
    int c  = (idx >> 7) & 127;
    int he = idx & 127;
    int h  = he >> 4, e2 = he & 15;
    // relation -> source node type: ti:taste(2), im:image(3), ub:user(0), bu:item(1)
    int tsrc = (r == 0) ? 2 : (r == 1) ? 3 : (r == 2) ? 0 : 1;
    const float* wrow = Wsrc + tsrc * 16384 + c * 128 + h * 16;
    const float* arow = rel + r * 2048 + h * 256;   // [d][e]
    float s = 0.f;
    #pragma unroll
    for (int d = 0; d < 16; d++) s += wrow[d] * arow[d * 16 + e2];
    Wout[idx] = s;
    if (c == 0) {
        const float* brow = bsrc + tsrc * 128 + h * 16;
        float sb = 0.f;
        #pragma unroll
        for (int d = 0; d < 16; d++) sb += brow[d] * arow[d * 16 + e2];
        bout[r * 128 + he] = sb;
    }
}

// ---------------------------------------------------------------------------
// GEMM: Y[N,128] = X[N,128] @ W[128,128] + bias, optional gated residual
// epilogue (mode 1): y = g*(acc+b) + (1-g)*Res, g = sigmoid(*SkipP)
// 256 threads, 64 rows x 128 cols per block, K chunked by 16.
// ---------------------------------------------------------------------------
__global__ void __launch_bounds__(256) gemm128_kernel(
        const float* __restrict__ X, const float* __restrict__ W,
        const float* __restrict__ Bias, float* __restrict__ Y, int N,
        int mode, const float* __restrict__ Res, const float* __restrict__ SkipP) {
    __shared__ float xs[16][68];
    __shared__ float ws[16][128];
    int t  = threadIdx.x;
    int tx = t & 31;       // col/4
    int ty = t >> 5;       // row-group of 8
    int rowBase = blockIdx.x * 64;

    float acc[8][4];
    #pragma unroll
    for (int r = 0; r < 8; r++)
        #pragma unroll
        for (int j = 0; j < 4; j++) acc[r][j] = 0.f;

    int lrow = t >> 2;        // 0..63
    int lk   = (t & 3) * 4;   // 0,4,8,12
    int wk   = t >> 4;        // 0..15
    int wc   = (t & 15) * 8;  // 0..120

    int grow = rowBase + lrow;
    for (int kc = 0; kc < 128; kc += 16) {
        float4 xv = make_float4(0.f, 0.f, 0.f, 0.f);
        if (grow < N) xv = *(const float4*)(X + (size_t)grow * 128 + kc + lk);
        float4 w0 = *(const float4*)(W + (size_t)(kc + wk) * 128 + wc);
        float4 w1 = *(const float4*)(W + (size_t)(kc + wk) * 128 + wc + 4);
        __syncthreads();
        xs[lk + 0][lrow] = xv.x; xs[lk + 1][lrow] = xv.y;
        xs[lk + 2][lrow] = xv.z; xs[lk + 3][lrow] = xv.w;
        *(float4*)&ws[wk][wc]     = w0;
        *(float4*)&ws[wk][wc + 4] = w1;
        __syncthreads();
        #pragma unroll
        for (int k = 0; k < 16; k++) {
            float4 wv = *(float4*)&ws[k][tx * 4];
            float4 xa = *(float4*)&xs[k][ty * 8];
            float4 xb = *(float4*)&xs[k][ty * 8 + 4];
            float xr[8] = {xa.x, xa.y, xa.z, xa.w, xb.x, xb.y, xb.z, xb.w};
            #pragma unroll
            for (int r = 0; r < 8; r++) {
                acc[r][0] += xr[r] * wv.x;
                acc[r][1] += xr[r] * wv.y;
                acc[r][2] += xr[r] * wv.z;
                acc[r][3] += xr[r] * wv.w;
            }
        }
    }

    float4 bv = *(const float4*)(Bias + tx * 4);
    float g = 1.f, omg = 0.f;
    if (mode == 1) { g = 1.f / (1.f + expf(-SkipP[0])); omg = 1.f - g; }
    #pragma unroll
    for (int r = 0; r < 8; r++) {
        int row = rowBase + ty * 8 + r;
        if (row >= N) continue;
        float4 o;
        o.x = acc[r][0] + bv.x; o.y = acc[r][1] + bv.y;
        o.z = acc[r][2] + bv.z; o.w = acc[r][3] + bv.w;
        if (mode == 1) {
            float4 rv = *(const float4*)(Res + (size_t)row * 128 + tx * 4);
            o.x = g * o.x + omg * rv.x; o.y = g * o.y + omg * rv.y;
            o.z = g * o.z + omg * rv.z; o.w = g * o.w + omg * rv.w;
        }
        *(float4*)(Y + (size_t)row * 128 + tx * 4) = o;
    }
}

// ---------------------------------------------------------------------------
// Edge pass: one warp per edge. Computes alpha per head, accumulates
// num[dst] += e^alpha * vr[src] and den[dst] += e^alpha via L2 reductions.
// ---------------------------------------------------------------------------
__global__ void __launch_bounds__(256) edge_kernel(
        const int* __restrict__ src, const int* __restrict__ dst, int E,
        const float* __restrict__ Q, const float* __restrict__ KR,
        const float* __restrict__ VR, float* __restrict__ num,
        float* __restrict__ den, const float* __restrict__ p) {
    int e = blockIdx.x * 8 + (threadIdx.x >> 5);
    if (e >= E) return;
    int lane = threadIdx.x & 31;
    int s = src[e], d = dst[e];
    float4 qv = *(const float4*)(Q  + (size_t)d * 128 + lane * 4);
    float4 kv = *(const float4*)(KR + (size_t)s * 128 + lane * 4);
    float part = qv.x * kv.x + qv.y * kv.y + qv.z * kv.z + qv.w * kv.w;
    // reduce over the 4 lanes of each head (16 dims)
    part += __shfl_xor_sync(0xFFFFFFFFu, part, 1);
    part += __shfl_xor_sync(0xFFFFFFFFu, part, 2);
    int h = lane >> 2;
    float alpha = part * p[h] * 0.25f;   // 1/sqrt(DH)=0.25
    float ex = expf(alpha);
    if ((lane & 3) == 0) atomicAdd(den + (size_t)d * 8 + h, ex);
    float4 vv = *(const float4*)(VR + (size_t)s * 128 + lane * 4);
    float* np = num + (size_t)d * 128 + lane * 4;
#if __CUDA_ARCH__ >= 900
    asm volatile("red.global.add.v4.f32 [%0], {%1, %2, %3, %4};"
                 :: "l"(np), "f"(ex * vv.x), "f"(ex * vv.y),
                    "f"(ex * vv.z), "f"(ex * vv.w)
                 : "memory");
#else
    atomicAdd(np + 0, ex * vv.x); atomicAdd(np + 1, ex * vv.y);
    atomicAdd(np + 2, ex * vv.z); atomicAdd(np + 3, ex * vv.w);
#endif
}

// ---------------------------------------------------------------------------
// agg = num/(den+eps), exact GELU
// ---------------------------------------------------------------------------
__global__ void gelu_div_kernel(const float* __restrict__ num,
                                const float* __restrict__ den,
                                float* __restrict__ out, int nElem) {
    int i = blockIdx.x * blockDim.x + threadIdx.x;
    if (i >= nElem) return;
    float dn = den[(size_t)(i >> 7) * 8 + ((i >> 4) & 7)];
    float v = num[i] / (dn + 1e-16f);
    out[i] = 0.5f * v * (1.f + erff(v * 0.70710678118654752f));
}

// ---------------------------------------------------------------------------
extern "C" void kernel_launch(void* const* d_in, const int* in_sizes, int n_in,
                              void* d_out, int out_size) {
    const float* x_user = (const float*)d_in[0];
    const float* x_item = (const float*)d_in[1];
    const float* x_taste = (const float*)d_in[2];
    const float* x_image = (const float*)d_in[3];
    const float* Wk = (const float*)d_in[4];
    const float* bk = (const float*)d_in[5];
    const float* Wq = (const float*)d_in[6];
    const float* bq = (const float*)d_in[7];
    const float* Wv = (const float*)d_in[8];
    const float* bv = (const float*)d_in[9];
    const float* a_rel = (const float*)d_in[10];
    const float* m_rel = (const float*)d_in[11];
    const float* p_rel = (const float*)d_in[12];
    const float* Wo = (const float*)d_in[13];
    const float* bo = (const float*)d_in[14];
    const float* skip = (const float*)d_in[15];
    const int* ti_src = (const int*)d_in[16];
    const int* ti_dst = (const int*)d_in[17];
    const int* im_src = (const int*)d_in[18];
    const int* im_dst = (const int*)d_in[19];
    const int* ub_src = (const int*)d_in[20];
    const int* ub_dst = (const int*)d_in[21];
    const int* bu_src = (const int*)d_in[22];
    const int* bu_dst = (const int*)d_in[23];

    int nUser = in_sizes[0] / HID;
    int nItem = in_sizes[1] / HID;
    int nTaste = in_sizes[2] / HID;
    int nImage = in_sizes[3] / HID;
    int eTI = in_sizes[16], eIM = in_sizes[18], eUB = in_sizes[20], eBU = in_sizes[22];

    float* S = nullptr;
    cudaGetSymbolAddress((void**)&S, g_scratch);

    // 1) zero accumulators (num_item..den_user contiguous: 9,520,000 floats)
    zero_kernel<<<2048, 256>>>((float4*)(S + OFF_NUM_ITEM), 9520000 / 4);

    // 2) fold relation matrices into projection weights
    fuse_rel_kernel<<<128, 512>>>(Wk, bk, a_rel, S + OFF_WKA, S + OFF_BKA);
    fuse_rel_kernel<<<128, 512>>>(Wv, bv, m_rel, S + OFF_WVM, S + OFF_BVM);

    // 3) projections (q for dst roles; fused kr/vr for src roles)
    #define GEMM(X, W, B, Y, N) \
        gemm128_kernel<<<((N) + 63) / 64, 256>>>(X, W, B, Y, N, 0, nullptr, nullptr)
    GEMM(x_user, Wq,               bq,              S + OFF_Q_USER,  nUser);
    GEMM(x_item, Wq + 16384,       bq + 128,        S + OFF_Q_ITEM,  nItem);
    GEMM(x_user, S + OFF_WKA + 2 * 16384, S + OFF_BKA + 2 * 128, S + OFF_KR_USER, nUser);
    GEMM(x_user, S + OFF_WVM + 2 * 16384, S + OFF_BVM + 2 * 128, S + OFF_VR_USER, nUser);
    GEMM(x_item, S + OFF_WKA + 3 * 16384, S + OFF_BKA + 3 * 128, S + OFF_KR_ITEM, nItem);
    GEMM(x_item, S + OFF_WVM + 3 * 16384, S + OFF_BVM + 3 * 128, S + OFF_VR_ITEM, nItem);
    GEMM(x_taste, S + OFF_WKA,            S + OFF_BKA,            S + OFF_KR_TASTE, nTaste);
    GEMM(x_taste, S + OFF_WVM,            S + OFF_BVM,            S + OFF_VR_TASTE, nTaste);
    GEMM(x_image, S + OFF_WKA + 16384,    S + OFF_BKA + 128,      S + OFF_KR_IMAGE, nImage);
    GEMM(x_image, S + OFF_WVM + 16384,    S + OFF_BVM + 128,      S + OFF_VR_IMAGE, nImage);
    #undef GEMM

    // 4) edge passes (single-pass softmax accumulation)
    edge_kernel<<<(eTI + 7) / 8, 256>>>(ti_src, ti_dst, eTI,
        S + OFF_Q_ITEM, S + OFF_KR_TASTE, S + OFF_VR_TASTE,
        S + OFF_NUM_ITEM, S + OFF_DEN_ITEM, p_rel + 0);
    edge_kernel<<<(eIM + 7) / 8, 256>>>(im_src, im_dst, eIM,
        S + OFF_Q_ITEM, S + OFF_KR_IMAGE, S + OFF_VR_IMAGE,
        S + OFF_NUM_ITEM, S + OFF_DEN_ITEM, p_rel + 8);
    edge_kernel<<<(eUB + 7) / 8, 256>>>(ub_src, ub_dst, eUB,
        S + OFF_Q_ITEM, S + OFF_KR_USER, S + OFF_VR_USER,
        S + OFF_NUM_ITEM, S + OFF_DEN_ITEM, p_rel + 16);
    edge_kernel<<<(eBU + 7) / 8, 256>>>(bu_src, bu_dst, eBU,
        S + OFF_Q_USER, S + OFF_KR_ITEM, S + OFF_VR_ITEM,
        S + OFF_NUM_USER, S + OFF_DEN_USER, p_rel + 24);

    // 5) normalize + GELU
    gelu_div_kernel<<<(nItem * HID + 255) / 256, 256>>>(
        S + OFF_NUM_ITEM, S + OFF_DEN_ITEM, S + OFF_GEL_ITEM, nItem * HID);
    gelu_div_kernel<<<(nUser * HID + 255) / 256, 256>>>(
        S + OFF_NUM_USER, S + OFF_DEN_USER, S + OFF_GEL_USER, nUser * HID);

    // 6) output projections with sigmoid-gated residual
    float* out_i = (float*)d_out;
    float* out_u = (float*)d_out + (size_t)nItem * HID;
    gemm128_kernel<<<(nItem + 63) / 64, 256>>>(
        S + OFF_GEL_ITEM, Wo, bo, out_i, nItem, 1, x_item, skip);
    gemm128_kernel<<<(nUser + 63) / 64, 256>>>(
        S + OFF_GEL_USER, Wo + 16384, bo + 128, out_u, nUser, 1, x_user, skip + 1);

    (void)n_in; (void)out_size;
}

// round 6
// speedup vs baseline: 1.4459x; 1.4459x over previous
#include <cuda_runtime.h>
#include <cuda_bf16.h>
#include <math.h>
#include <stdint.h>

// ---------------------------------------------------------------------------
// MultiModalFusionGAT — mma.sync bf16x3-split GEMM version.
// (Harness compiles for plain sm_100: tcgen05/TMEM are unavailable — R4 ptxas
//  evidence. HMMA via mma.sync.m16n8k16 is the tensor-core path that works.)
//  * relation transform folded into projection weights at prep time
//  * prep kernel writes weights directly in mma B-fragment-linear layout
//    (bf16 hi/lo pairs) -> conflict-free LDS.64 in the GEMM, no ldmatrix
//  * GEMM: 3-term bf16 split  X@W ~= Xh@Wh + Xl@Wh + Xh@Wl  (rel err ~2^-17)
//  * segment softmax as a single atomic pass (max-subtraction cancels exactly)
// ---------------------------------------------------------------------------

#define HID 128
#define NH  8
#define DH  16

// scratch layout (floats)
#define OFF_Q_USER   0ll
#define OFF_Q_ITEM   2560000ll
#define OFF_KR_USER  8960000ll
#define OFF_VR_USER  11520000ll
#define OFF_KR_ITEM  14080000ll
#define OFF_VR_ITEM  20480000ll
#define OFF_KR_TASTE 26880000ll
#define OFF_VR_TASTE 33280000ll
#define OFF_KR_IMAGE 39680000ll
#define OFF_VR_IMAGE 46080000ll
#define OFF_NUM_ITEM 52480000ll
#define OFF_DEN_ITEM 58880000ll
#define OFF_NUM_USER 59280000ll
#define OFF_DEN_USER 61840000ll
#define OFF_GEL_ITEM 62000000ll
#define OFF_GEL_USER 68400000ll
#define OFF_WFRAG    70960000ll   // 12 mats x 16384 u32 (hi 8192 + lo 8192)
#define OFF_BIAS     71156608ll   // 12 x 128 floats
#define SCRATCH_TOTAL 71158144ll

__device__ float g_scratch[SCRATCH_TOTAL];

// ---------------------------------------------------------------------------
__global__ void zero_kernel(float4* __restrict__ p, int n4) {
    int i = blockIdx.x * blockDim.x + threadIdx.x;
    int stride = gridDim.x * blockDim.x;
    float4 z = make_float4(0.f, 0.f, 0.f, 0.f);
    for (; i < n4; i += stride) p[i] = z;
}

// Folded weight element W[k][n] for matrix m (0-7 fused k/v, 8-9 Wq, 10-11 Wo)
__device__ __forceinline__ float foldW(int m, int k, int n,
        const float* __restrict__ Wk, const float* __restrict__ Wv,
        const float* __restrict__ Wq, const float* __restrict__ Wo,
        const float* __restrict__ a_rel, const float* __restrict__ m_rel) {
    if (m < 8) {
        int r = m & 3;
        int h = n >> 4, e = n & 15;
        int tsrc = (r == 0) ? 2 : (r == 1) ? 3 : (r == 2) ? 0 : 1;
        const float* Wsrc = (m < 4) ? Wk : Wv;
        const float* rel  = (m < 4) ? a_rel : m_rel;
        const float* wrow = Wsrc + tsrc * 16384 + k * 128 + h * 16;
        const float* arow = rel + r * 2048 + h * 256;
        float s = 0.f;
        #pragma unroll
        for (int d = 0; d < 16; d++) s += wrow[d] * arow[d * 16 + e];
        return s;
    } else if (m < 10) {
        return Wq[(m - 8) * 16384 + k * 128 + n];
    }
    return Wo[(m - 10) * 16384 + k * 128 + n];
}

__device__ __forceinline__ uint32_t packbf2(float a, float b) {
    __nv_bfloat16 ha = __float2bfloat16(a), hb = __float2bfloat16(b);
    return (uint32_t)__bfloat16_as_ushort(ha)
         | ((uint32_t)__bfloat16_as_ushort(hb) << 16);
}

// prep: write W in mma B-fragment-linear layout.
// mma.m16n8k16.row.col B fragment (PTX ISA):
//   reg r=0: k = kc*16 + (lane%4)*2 + {0,1}, n = nt*8 + lane/4
//   reg r=1: same n, k + 8
// Layout: mat block 16384 u32 = hi[kc][nt][lane][r] (8192) then lo (8192).
__global__ void prep_kernel(const float* __restrict__ Wk, const float* __restrict__ bk,
                            const float* __restrict__ Wq, const float* __restrict__ bq,
                            const float* __restrict__ Wv, const float* __restrict__ bv,
                            const float* __restrict__ a_rel, const float* __restrict__ m_rel,
                            const float* __restrict__ Wo, const float* __restrict__ bo,
                            uint32_t* __restrict__ Wfrag, float* __restrict__ Bias) {
    int idx = blockIdx.x * blockDim.x + threadIdx.x;
    if (idx < 98304) {
        int m = idx >> 13;            // /8192
        int rest = idx & 8191;
        int kc = rest >> 10;          // /1024
        int rest2 = rest & 1023;
        int nt = rest2 >> 6;          // /64
        int e  = rest2 & 63;
        int lane = e >> 1, r = e & 1;
        int n  = nt * 8 + (lane >> 2);
        int k0 = kc * 16 + (lane & 3) * 2 + r * 8;
        float v0 = foldW(m, k0,     n, Wk, Wv, Wq, Wo, a_rel, m_rel);
        float v1 = foldW(m, k0 + 1, n, Wk, Wv, Wq, Wo, a_rel, m_rel);
        __nv_bfloat16 h0 = __float2bfloat16(v0), h1 = __float2bfloat16(v1);
        float l0 = v0 - __bfloat162float(h0), l1 = v1 - __bfloat162float(h1);
        uint32_t hi = (uint32_t)__bfloat16_as_ushort(h0)
                    | ((uint32_t)__bfloat16_as_ushort(h1) << 16);
        uint32_t lo = packbf2(l0, l1);
        size_t base = (size_t)m * 16384 + ((kc * 16 + nt) * 64 + e);
        Wfrag[base] = hi;
        Wfrag[base + 8192] = lo;
    } else if (idx < 98304 + 1536) {
        int j = idx - 98304;
        int m = j >> 7, n = j & 127;
        float bval;
        if (m < 8) {
            int r = m & 3;
            int h = n >> 4, e2 = n & 15;
            int tsrc = (r == 0) ? 2 : (r == 1) ? 3 : (r == 2) ? 0 : 1;
            const float* bsrc = (m < 4) ? bk : bv;
            const float* rel  = (m < 4) ? a_rel : m_rel;
            const float* brow = bsrc + tsrc * 128 + h * 16;
            const float* arow = rel + r * 2048 + h * 256;
            float sb = 0.f;
            #pragma unroll
            for (int d = 0; d < 16; d++) sb += brow[d] * arow[d * 16 + e2];
            bval = sb;
        } else if (m < 10) {
            bval = bq[(m - 8) * 128 + n];
        } else {
            bval = bo[(m - 10) * 128 + n];
        }
        Bias[m * 128 + n] = bval;
    }
}

// ---------------------------------------------------------------------------
__device__ __forceinline__ void mma16816(float c[4], const uint32_t a[4],
                                         uint32_t b0, uint32_t b1) {
    asm volatile(
        "mma.sync.aligned.m16n8k16.row.col.f32.bf16.bf16.f32 "
        "{%0,%1,%2,%3}, {%4,%5,%6,%7}, {%8,%9}, {%0,%1,%2,%3};"
        : "+f"(c[0]), "+f"(c[1]), "+f"(c[2]), "+f"(c[3])
        : "r"(a[0]), "r"(a[1]), "r"(a[2]), "r"(a[3]), "r"(b0), "r"(b1));
}

// GEMM: Y[N,128] = X[N,128] @ W[128,128] + bias (+ gated residual for mode 1)
// CTA: 256 threads / 8 warps; warp = 16 rows. W fragments staged in smem.
#define GEMM_SMEM 65536
__global__ void __launch_bounds__(256) mma_gemm_kernel(
        const float* __restrict__ X, const uint32_t* __restrict__ Wfrag,
        const float* __restrict__ Bias, float* __restrict__ Y, int N, int mode,
        const float* __restrict__ Res, const float* __restrict__ SkipP) {
    extern __shared__ uint32_t sW[];   // 16384 u32: hi 8192 | lo 8192
    int tid = threadIdx.x;

    {   // cooperative 64 KB weight-fragment load
        const uint4* src = (const uint4*)Wfrag;
        uint4* dst = (uint4*)sW;
        #pragma unroll
        for (int i = 0; i < 16; i++) dst[tid + i * 256] = src[tid + i * 256];
    }
    __syncthreads();

    int warp = tid >> 5, lane = tid & 31;
    int rlo = blockIdx.x * 128 + warp * 16 + (lane >> 2);
    int rhi = rlo + 8;
    bool oklo = rlo < N, okhi = rhi < N;
    const float* xlo = X + (size_t)rlo * 128;
    const float* xhi = X + (size_t)rhi * 128;

    float C[16][4];
    #pragma unroll
    for (int nt = 0; nt < 16; nt++)
        #pragma unroll
        for (int j = 0; j < 4; j++) C[nt][j] = 0.f;

    int kb = (lane & 3) * 2;
    #pragma unroll 1
    for (int kc = 0; kc < 8; kc++) {
        float2 v00 = oklo ? *(const float2*)(xlo + kc * 16 + kb)
                          : make_float2(0.f, 0.f);
        float2 v01 = oklo ? *(const float2*)(xlo + kc * 16 + kb + 8)
                          : make_float2(0.f, 0.f);
        float2 v10 = okhi ? *(const float2*)(xhi + kc * 16 + kb)
                          : make_float2(0.f, 0.f);
        float2 v11 = okhi ? *(const float2*)(xhi + kc * 16 + kb + 8)
                          : make_float2(0.f, 0.f);
        uint32_t ahi[4], alo[4];
        {
            __nv_bfloat16 h, h2;
            float r0, r1;
            h  = __float2bfloat16(v00.x); r0 = v00.x - __bfloat162float(h);
            h2 = __float2bfloat16(v00.y); r1 = v00.y - __bfloat162float(h2);
            ahi[0] = (uint32_t)__bfloat16_as_ushort(h)
                   | ((uint32_t)__bfloat16_as_ushort(h2) << 16);
            alo[0] = packbf2(r0, r1);
            h  = __float2bfloat16(v10.x); r0 = v10.x - __bfloat162float(h);
            h2 = __float2bfloat16(v10.y); r1 = v10.y - __bfloat162float(h2);
            ahi[1] = (uint32_t)__bfloat16_as_ushort(h)
                   | ((uint32_t)__bfloat16_as_ushort(h2) << 16);
            alo[1] = packbf2(r0, r1);
            h  = __float2bfloat16(v01.x); r0 = v01.x - __bfloat162float(h);
            h2 = __float2bfloat16(v01.y); r1 = v01.y - __bfloat162float(h2);
            ahi[2] = (uint32_t)__bfloat16_as_ushort(h)
                   | ((uint32_t)__bfloat16_as_ushort(h2) << 16);
            alo[2] = packbf2(r0, r1);
            h  = __float2bfloat16(v11.x); r0 = v11.x - __bfloat162float(h);
            h2 = __float2bfloat16(v11.y); r1 = v11.y - __bfloat162float(h2);
            ahi[3] = (uint32_t)__bfloat16_as_ushort(h)
                   | ((uint32_t)__bfloat16_as_ushort(h2) << 16);
            alo[3] = packbf2(r0, r1);
        }
        #pragma unroll
        for (int nt = 0; nt < 16; nt++) {
            uint32_t off = (uint32_t)((kc * 16 + nt) * 64 + lane * 2);
            uint2 bh = *(const uint2*)&sW[off];
            uint2 bl = *(const uint2*)&sW[off + 8192];
            mma16816(C[nt], ahi, bh.x, bh.y);
            mma16816(C[nt], alo, bh.x, bh.y);
            mma16816(C[nt], ahi, bl.x, bl.y);
        }
    }

    float g = 1.f, omg = 0.f;
    if (mode == 1) { g = 1.f / (1.f + expf(-SkipP[0])); omg = 1.f - g; }

    #pragma unroll
    for (int nt = 0; nt < 16; nt++) {
        int col = nt * 8 + kb;
        float2 b = *(const float2*)(Bias + col);
        if (oklo) {
            float2 o = make_float2(C[nt][0] + b.x, C[nt][1] + b.y);
            if (mode == 1) {
                float2 rv = *(const float2*)(Res + (size_t)rlo * 128 + col);
                o.x = g * o.x + omg * rv.x;
                o.y = g * o.y + omg * rv.y;
            }
            *(float2*)(Y + (size_t)rlo * 128 + col) = o;
        }
        if (okhi) {
            float2 o = make_float2(C[nt][2] + b.x, C[nt][3] + b.y);
            if (mode == 1) {
                float2 rv = *(const float2*)(Res + (size_t)rhi * 128 + col);
                o.x = g * o.x + omg * rv.x;
                o.y = g * o.y + omg * rv.y;
            }
            *(float2*)(Y + (size_t)rhi * 128 + col) = o;
        }
    }
}

// ---------------------------------------------------------------------------
// edge pass: one warp per edge, single-pass softmax accumulation
__global__ void __launch_bounds__(256) edge_kernel(
        const int* __restrict__ src, const int* __restrict__ dst, int E,
        const float* __restrict__ Q, const float* __restrict__ KR,
        const float* __restrict__ VR, float* __restrict__ num,
        float* __restrict__ den, const float* __restrict__ p) {
    int e = blockIdx.x * 8 + (threadIdx.x >> 5);
    if (e >= E) return;
    int lane = threadIdx.x & 31;
    int s = src[e], d = dst[e];
    float4 qv = *(const float4*)(Q + (size_t)d * 128 + lane * 4);
    float4 kv = *(const float4*)(KR + (size_t)s * 128 + lane * 4);
    float part = qv.x * kv.x + qv.y * kv.y + qv.z * kv.z + qv.w * kv.w;
    part += __shfl_xor_sync(0xFFFFFFFFu, part, 1);
    part += __shfl_xor_sync(0xFFFFFFFFu, part, 2);
    int h = lane >> 2;
    float alpha = part * p[h] * 0.25f;
    float ex = expf(alpha);
    if ((lane & 3) == 0) atomicAdd(den + (size_t)d * 8 + h, ex);
    float4 vv = *(const float4*)(VR + (size_t)s * 128 + lane * 4);
    float* np = num + (size_t)d * 128 + lane * 4;
    asm volatile("red.global.add.v4.f32 [%0], {%1, %2, %3, %4};"
                 :: "l"(np), "f"(ex * vv.x), "f"(ex * vv.y),
                    "f"(ex * vv.z), "f"(ex * vv.w) : "memory");
}

__global__ void gelu_div_kernel(const float* __restrict__ num,
                                const float* __restrict__ den,
                                float* __restrict__ out, int nElem) {
    int i = blockIdx.x * blockDim.x + threadIdx.x;
    if (i >= nElem) return;
    float dn = den[(size_t)(i >> 7) * 8 + ((i >> 4) & 7)];
    float v = num[i] / (dn + 1e-16f);
    out[i] = 0.5f * v * (1.f + erff(v * 0.70710678118654752f));
}

// ---------------------------------------------------------------------------
extern "C" void kernel_launch(void* const* d_in, const int* in_sizes, int n_in,
                              void* d_out, int out_size) {
    const float* x_user = (const float*)d_in[0];
    const float* x_item = (const float*)d_in[1];
    const float* x_taste = (const float*)d_in[2];
    const float* x_image = (const float*)d_in[3];
    const float* Wk = (const float*)d_in[4];
    const float* bk = (const float*)d_in[5];
    const float* Wq = (const float*)d_in[6];
    const float* bq = (const float*)d_in[7];
    const float* Wv = (const float*)d_in[8];
    const float* bv = (const float*)d_in[9];
    const float* a_rel = (const float*)d_in[10];
    const float* m_rel = (const float*)d_in[11];
    const float* p_rel = (const float*)d_in[12];
    const float* Wo = (const float*)d_in[13];
    const float* bo = (const float*)d_in[14];
    const float* skip = (const float*)d_in[15];
    const int* ti_src = (const int*)d_in[16];
    const int* ti_dst = (const int*)d_in[17];
    const int* im_src = (const int*)d_in[18];
    const int* im_dst = (const int*)d_in[19];
    const int* ub_src = (const int*)d_in[20];
    const int* ub_dst = (const int*)d_in[21];
    const int* bu_src = (const int*)d_in[22];
    const int* bu_dst = (const int*)d_in[23];

    int nUser = in_sizes[0] / HID;
    int nItem = in_sizes[1] / HID;
    int nTaste = in_sizes[2] / HID;
    int nImage = in_sizes[3] / HID;
    int eTI = in_sizes[16], eIM = in_sizes[18], eUB = in_sizes[20], eBU = in_sizes[22];

    float* S = nullptr;
    cudaGetSymbolAddress((void**)&S, g_scratch);
    uint32_t* Wfrag = (uint32_t*)(S + OFF_WFRAG);

    cudaFuncSetAttribute(mma_gemm_kernel,
                         cudaFuncAttributeMaxDynamicSharedMemorySize, GEMM_SMEM);

    // 1) zero accumulators (num_item..den_user contiguous: 9,520,000 floats)
    zero_kernel<<<2048, 256>>>((float4*)(S + OFF_NUM_ITEM), 9520000 / 4);

    // 2) prep weights into fragment layout (+ bias fold)
    prep_kernel<<<(98304 + 1536 + 255) / 256, 256>>>(
        Wk, bk, Wq, bq, Wv, bv, a_rel, m_rel, Wo, bo, Wfrag, S + OFF_BIAS);

    // 3) tensor-core projections
    #define TCGEMM(Xp, mat, Yp, Nn, md, Rs, Sk)                               \
        mma_gemm_kernel<<<((Nn) + 127) / 128, 256, GEMM_SMEM>>>(Xp,           \
            Wfrag + (size_t)(mat) * 16384,                                    \
            S + OFF_BIAS + (mat) * 128, Yp, Nn, md, Rs, Sk)

    TCGEMM(x_user,  8, S + OFF_Q_USER,   nUser,  0, nullptr, nullptr);
    TCGEMM(x_item,  9, S + OFF_Q_ITEM,   nItem,  0, nullptr, nullptr);
    TCGEMM(x_user,  2, S + OFF_KR_USER,  nUser,  0, nullptr, nullptr);
    TCGEMM(x_user,  6, S + OFF_VR_USER,  nUser,  0, nullptr, nullptr);
    TCGEMM(x_item,  3, S + OFF_KR_ITEM,  nItem,  0, nullptr, nullptr);
    TCGEMM(x_item,  7, S + OFF_VR_ITEM,  nItem,  0, nullptr, nullptr);
    TCGEMM(x_taste, 0, S + OFF_KR_TASTE, nTaste, 0, nullptr, nullptr);
    TCGEMM(x_taste, 4, S + OFF_VR_TASTE, nTaste, 0, nullptr, nullptr);
    TCGEMM(x_image, 1, S + OFF_KR_IMAGE, nImage, 0, nullptr, nullptr);
    TCGEMM(x_image, 5, S + OFF_VR_IMAGE, nImage, 0, nullptr, nullptr);

    // 4) edge passes
    edge_kernel<<<(eTI + 7) / 8, 256>>>(ti_src, ti_dst, eTI,
        S + OFF_Q_ITEM, S + OFF_KR_TASTE, S + OFF_VR_TASTE,
        S + OFF_NUM_ITEM, S + OFF_DEN_ITEM, p_rel + 0);
    edge_kernel<<<(eIM + 7) / 8, 256>>>(im_src, im_dst, eIM,
        S + OFF_Q_ITEM, S + OFF_KR_IMAGE, S + OFF_VR_IMAGE,
        S + OFF_NUM_ITEM, S + OFF_DEN_ITEM, p_rel + 8);
    edge_kernel<<<(eUB + 7) / 8, 256>>>(ub_src, ub_dst, eUB,
        S + OFF_Q_ITEM, S + OFF_KR_USER, S + OFF_VR_USER,
        S + OFF_NUM_ITEM, S + OFF_DEN_ITEM, p_rel + 16);
    edge_kernel<<<(eBU + 7) / 8, 256>>>(bu_src, bu_dst, eBU,
        S + OFF_Q_USER, S + OFF_KR_ITEM, S + OFF_VR_ITEM,
        S + OFF_NUM_USER, S + OFF_DEN_USER, p_rel + 24);

    // 5) normalize + GELU
    gelu_div_kernel<<<(nItem * HID + 255) / 256, 256>>>(
        S + OFF_NUM_ITEM, S + OFF_DEN_ITEM, S + OFF_GEL_ITEM, nItem * HID);
    gelu_div_kernel<<<(nUser * HID + 255) / 256, 256>>>(
        S + OFF_NUM_USER, S + OFF_DEN_USER, S + OFF_GEL_USER, nUser * HID);

    // 6) output projections with sigmoid-gated residual
    float* out_i = (float*)d_out;
    float* out_u = (float*)d_out + (size_t)nItem * HID;
    TCGEMM(S + OFF_GEL_ITEM, 10, out_i, nItem, 1, x_item, skip);
    TCGEMM(S + OFF_GEL_USER, 11, out_u, nUser, 1, x_user, skip + 1);
    #undef TCGEMM

    (void)n_in; (void)out_size;
}

// round 7
// speedup vs baseline: 1.6125x; 1.1152x over previous
#include <cuda_runtime.h>
#include <cuda_bf16.h>
#include <math.h>
#include <stdint.h>

// ---------------------------------------------------------------------------
// MultiModalFusionGAT — mma.sync bf16x3 GEMM, batched single-launch version.
//  * all 10 projection GEMMs in ONE kernel launch (grid.y = matrix)
//  * kc loop software-pipelined (register double-buffer of X loads)
//  * all 4 edge passes in ONE launch (segment select); gelu passes merged
// ---------------------------------------------------------------------------

#define HID 128

// scratch layout (floats)
#define OFF_Q_USER   0ll
#define OFF_Q_ITEM   2560000ll
#define OFF_KR_USER  8960000ll
#define OFF_VR_USER  11520000ll
#define OFF_KR_ITEM  14080000ll
#define OFF_VR_ITEM  20480000ll
#define OFF_KR_TASTE 26880000ll
#define OFF_VR_TASTE 33280000ll
#define OFF_KR_IMAGE 39680000ll
#define OFF_VR_IMAGE 46080000ll
#define OFF_NUM_ITEM 52480000ll
#define OFF_DEN_ITEM 58880000ll
#define OFF_NUM_USER 59280000ll
#define OFF_DEN_USER 61840000ll
#define OFF_GEL_ITEM 62000000ll
#define OFF_GEL_USER 68400000ll
#define OFF_WFRAG    70960000ll   // 12 mats x 16384 u32 (hi 8192 + lo 8192)
#define OFF_BIAS     71156608ll   // 12 x 128 floats
#define SCRATCH_TOTAL 71158144ll

__device__ float g_scratch[SCRATCH_TOTAL];

struct GemmBatch {
    const float* X[10];
    const uint32_t* W[10];
    const float* B[10];
    float* Y[10];
    int N[10];
};

struct EdgeBatch {
    const int* src[4];
    const int* dst[4];
    const float* Q[4];
    const float* KR[4];
    const float* VR[4];
    float* num[4];
    float* den[4];
    const float* prel;   // p_rel base; seg*8+h
    int off[5];          // prefix sums of edge counts
};

// ---------------------------------------------------------------------------
__global__ void zero_kernel(float4* __restrict__ p, int n4) {
    int i = blockIdx.x * blockDim.x + threadIdx.x;
    int stride = gridDim.x * blockDim.x;
    float4 z = make_float4(0.f, 0.f, 0.f, 0.f);
    for (; i < n4; i += stride) p[i] = z;
}

// Folded weight element W[k][n] for matrix m (0-7 fused k/v, 8-9 Wq, 10-11 Wo)
__device__ __forceinline__ float foldW(int m, int k, int n,
        const float* __restrict__ Wk, const float* __restrict__ Wv,
        const float* __restrict__ Wq, const float* __restrict__ Wo,
        const float* __restrict__ a_rel, const float* __restrict__ m_rel) {
    if (m < 8) {
        int r = m & 3;
        int h = n >> 4, e = n & 15;
        int tsrc = (r == 0) ? 2 : (r == 1) ? 3 : (r == 2) ? 0 : 1;
        const float* Wsrc = (m < 4) ? Wk : Wv;
        const float* rel  = (m < 4) ? a_rel : m_rel;
        const float* wrow = Wsrc + tsrc * 16384 + k * 128 + h * 16;
        const float* arow = rel + r * 2048 + h * 256;
        float s = 0.f;
        #pragma unroll
        for (int d = 0; d < 16; d++) s += wrow[d] * arow[d * 16 + e];
        return s;
    } else if (m < 10) {
        return Wq[(m - 8) * 16384 + k * 128 + n];
    }
    return Wo[(m - 10) * 16384 + k * 128 + n];
}

__device__ __forceinline__ uint32_t packbf2(float a, float b) {
    __nv_bfloat16 ha = __float2bfloat16(a), hb = __float2bfloat16(b);
    return (uint32_t)__bfloat16_as_ushort(ha)
         | ((uint32_t)__bfloat16_as_ushort(hb) << 16);
}

// prep: write W in mma B-fragment-linear layout (hi 8192 u32 | lo 8192 u32).
__global__ void prep_kernel(const float* __restrict__ Wk, const float* __restrict__ bk,
                            const float* __restrict__ Wq, const float* __restrict__ bq,
                            const float* __restrict__ Wv, const float* __restrict__ bv,
                            const float* __restrict__ a_rel, const float* __restrict__ m_rel,
                            const float* __restrict__ Wo, const float* __restrict__ bo,
                            uint32_t* __restrict__ Wfrag, float* __restrict__ Bias) {
    int idx = blockIdx.x * blockDim.x + threadIdx.x;
    if (idx < 98304) {
        int m = idx >> 13;
        int rest = idx & 8191;
        int kc = rest >> 10;
        int rest2 = rest & 1023;
        int nt = rest2 >> 6;
        int e  = rest2 & 63;
        int lane = e >> 1, r = e & 1;
        int n  = nt * 8 + (lane >> 2);
        int k0 = kc * 16 + (lane & 3) * 2 + r * 8;
        float v0 = foldW(m, k0,     n, Wk, Wv, Wq, Wo, a_rel, m_rel);
        float v1 = foldW(m, k0 + 1, n, Wk, Wv, Wq, Wo, a_rel, m_rel);
        __nv_bfloat16 h0 = __float2bfloat16(v0), h1 = __float2bfloat16(v1);
        float l0 = v0 - __bfloat162float(h0), l1 = v1 - __bfloat162float(h1);
        uint32_t hi = (uint32_t)__bfloat16_as_ushort(h0)
                    | ((uint32_t)__bfloat16_as_ushort(h1) << 16);
        uint32_t lo = packbf2(l0, l1);
        size_t base = (size_t)m * 16384 + ((kc * 16 + nt) * 64 + e);
        Wfrag[base] = hi;
        Wfrag[base + 8192] = lo;
    } else if (idx < 98304 + 1536) {
        int j = idx - 98304;
        int m = j >> 7, n = j & 127;
        float bval;
        if (m < 8) {
            int r = m & 3;
            int h = n >> 4, e2 = n & 15;
            int tsrc = (r == 0) ? 2 : (r == 1) ? 3 : (r == 2) ? 0 : 1;
            const float* bsrc = (m < 4) ? bk : bv;
            const float* rel  = (m < 4) ? a_rel : m_rel;
            const float* brow = bsrc + tsrc * 128 + h * 16;
            const float* arow = rel + r * 2048 + h * 256;
            float sb = 0.f;
            #pragma unroll
            for (int d = 0; d < 16; d++) sb += brow[d] * arow[d * 16 + e2];
            bval = sb;
        } else if (m < 10) {
            bval = bq[(m - 8) * 128 + n];
        } else {
            bval = bo[(m - 10) * 128 + n];
        }
        Bias[m * 128 + n] = bval;
    }
}

// ---------------------------------------------------------------------------
__device__ __forceinline__ void mma16816(float c[4], const uint32_t a[4],
                                         uint32_t b0, uint32_t b1) {
    asm volatile(
        "mma.sync.aligned.m16n8k16.row.col.f32.bf16.bf16.f32 "
        "{%0,%1,%2,%3}, {%4,%5,%6,%7}, {%8,%9}, {%0,%1,%2,%3};"
        : "+f"(c[0]), "+f"(c[1]), "+f"(c[2]), "+f"(c[3])
        : "r"(a[0]), "r"(a[1]), "r"(a[2]), "r"(a[3]), "r"(b0), "r"(b1));
}

__device__ __forceinline__ void split4(const float2& a, const float2& b,
                                       uint32_t& h01, uint32_t& l01,
                                       uint32_t& h23, uint32_t& l23) {
    __nv_bfloat16 ha = __float2bfloat16(a.x), hb = __float2bfloat16(a.y);
    __nv_bfloat16 hc = __float2bfloat16(b.x), hd = __float2bfloat16(b.y);
    h01 = (uint32_t)__bfloat16_as_ushort(ha) | ((uint32_t)__bfloat16_as_ushort(hb) << 16);
    h23 = (uint32_t)__bfloat16_as_ushort(hc) | ((uint32_t)__bfloat16_as_ushort(hd) << 16);
    l01 = packbf2(a.x - __bfloat162float(ha), a.y - __bfloat162float(hb));
    l23 = packbf2(b.x - __bfloat162float(hc), b.y - __bfloat162float(hd));
}

// Core 128-row x 128-col tile GEMM body (bf16x3), software-pipelined kc loop.
// mode==1 adds sigmoid-gated residual.
__device__ __forceinline__ void gemm_tile(
        const float* __restrict__ X, const uint32_t* __restrict__ sW,
        const float* __restrict__ Bias, float* __restrict__ Y, int N, int tile0,
        int mode, const float* __restrict__ Res, float g, float omg) {
    int tid = threadIdx.x;
    int warp = tid >> 5, lane = tid & 31;
    int rlo = tile0 + warp * 16 + (lane >> 2);
    int rhi = rlo + 8;
    bool oklo = rlo < N, okhi = rhi < N;
    const float* xlo = X + (size_t)rlo * 128;
    const float* xhi = X + (size_t)rhi * 128;
    int kb = (lane & 3) * 2;

    float C[16][4];
    #pragma unroll
    for (int nt = 0; nt < 16; nt++)
        #pragma unroll
        for (int j = 0; j < 4; j++) C[nt][j] = 0.f;

    float2 z2 = make_float2(0.f, 0.f);
    // prefetch kc=0
    float2 p00 = oklo ? *(const float2*)(xlo + kb)     : z2;
    float2 p01 = oklo ? *(const float2*)(xlo + kb + 8) : z2;
    float2 p10 = okhi ? *(const float2*)(xhi + kb)     : z2;
    float2 p11 = okhi ? *(const float2*)(xhi + kb + 8) : z2;

    #pragma unroll 1
    for (int kc = 0; kc < 8; kc++) {
        float2 c00 = p00, c01 = p01, c10 = p10, c11 = p11;
        if (kc < 7) {   // prefetch next kc while MMA chain runs
            int o = (kc + 1) * 16 + kb;
            p00 = oklo ? *(const float2*)(xlo + o)     : z2;
            p01 = oklo ? *(const float2*)(xlo + o + 8) : z2;
            p10 = okhi ? *(const float2*)(xhi + o)     : z2;
            p11 = okhi ? *(const float2*)(xhi + o + 8) : z2;
        }
        uint32_t ahi[4], alo[4];
        split4(c00, c10, ahi[0], alo[0], ahi[1], alo[1]);
        split4(c01, c11, ahi[2], alo[2], ahi[3], alo[3]);
        #pragma unroll
        for (int nt = 0; nt < 16; nt++) {
            uint32_t off = (uint32_t)((kc * 16 + nt) * 64 + lane * 2);
            uint2 bh = *(const uint2*)&sW[off];
            uint2 bl = *(const uint2*)&sW[off + 8192];
            mma16816(C[nt], ahi, bh.x, bh.y);
            mma16816(C[nt], alo, bh.x, bh.y);
            mma16816(C[nt], ahi, bl.x, bl.y);
        }
    }

    #pragma unroll
    for (int nt = 0; nt < 16; nt++) {
        int col = nt * 8 + kb;
        float2 b = *(const float2*)(Bias + col);
        if (oklo) {
            float2 o = make_float2(C[nt][0] + b.x, C[nt][1] + b.y);
            if (mode == 1) {
                float2 rv = *(const float2*)(Res + (size_t)rlo * 128 + col);
                o.x = g * o.x + omg * rv.x;
                o.y = g * o.y + omg * rv.y;
            }
            *(float2*)(Y + (size_t)rlo * 128 + col) = o;
        }
        if (okhi) {
            float2 o = make_float2(C[nt][2] + b.x, C[nt][3] + b.y);
            if (mode == 1) {
                float2 rv = *(const float2*)(Res + (size_t)rhi * 128 + col);
                o.x = g * o.x + omg * rv.x;
                o.y = g * o.y + omg * rv.y;
            }
            *(float2*)(Y + (size_t)rhi * 128 + col) = o;
        }
    }
}

#define GEMM_SMEM 65536

// batched projections: grid.y = matrix id (0..9), grid.x = row tile
__global__ void __launch_bounds__(256) mma_gemm_batch(GemmBatch P) {
    int m = blockIdx.y;
    int N = P.N[m];
    int tile0 = blockIdx.x * 128;
    if (tile0 >= N) return;
    extern __shared__ uint32_t sW[];
    {
        const uint4* src = (const uint4*)P.W[m];
        uint4* dst = (uint4*)sW;
        int tid = threadIdx.x;
        #pragma unroll
        for (int i = 0; i < 16; i++) dst[tid + i * 256] = src[tid + i * 256];
    }
    __syncthreads();
    gemm_tile(P.X[m], sW, P.B[m], P.Y[m], N, tile0, 0, nullptr, 1.f, 0.f);
}

// single-mat output GEMM with sigmoid-gated residual
__global__ void __launch_bounds__(256) mma_gemm_out(
        const float* __restrict__ X, const uint32_t* __restrict__ Wfrag,
        const float* __restrict__ Bias, float* __restrict__ Y, int N,
        const float* __restrict__ Res, const float* __restrict__ SkipP) {
    extern __shared__ uint32_t sW[];
    {
        const uint4* src = (const uint4*)Wfrag;
        uint4* dst = (uint4*)sW;
        int tid = threadIdx.x;
        #pragma unroll
        for (int i = 0; i < 16; i++) dst[tid + i * 256] = src[tid + i * 256];
    }
    __syncthreads();
    float g = 1.f / (1.f + expf(-SkipP[0]));
    gemm_tile(X, sW, Bias, Y, N, blockIdx.x * 128, 1, Res, g, 1.f - g);
}

// ---------------------------------------------------------------------------
// merged edge pass: one warp per edge, 4 segments, single-pass softmax accum
__global__ void __launch_bounds__(256) edge_batch(EdgeBatch P) {
    int g = blockIdx.x * 8 + (threadIdx.x >> 5);
    if (g >= P.off[4]) return;
    int seg = (g >= P.off[1]) + (g >= P.off[2]) + (g >= P.off[3]);
    int e = g - P.off[seg];
    int lane = threadIdx.x & 31;
    int s = P.src[seg][e], d = P.dst[seg][e];
    const float* Q  = P.Q[seg];
    const float* KR = P.KR[seg];
    const float* VR = P.VR[seg];
    float4 qv = *(const float4*)(Q + (size_t)d * 128 + lane * 4);
    float4 kv = *(const float4*)(KR + (size_t)s * 128 + lane * 4);
    float part = qv.x * kv.x + qv.y * kv.y + qv.z * kv.z + qv.w * kv.w;
    part += __shfl_xor_sync(0xFFFFFFFFu, part, 1);
    part += __shfl_xor_sync(0xFFFFFFFFu, part, 2);
    int h = lane >> 2;
    float alpha = part * P.prel[seg * 8 + h] * 0.25f;
    float ex = expf(alpha);
    if ((lane & 3) == 0) atomicAdd(P.den[seg] + (size_t)d * 8 + h, ex);
    float4 vv = *(const float4*)(VR + (size_t)s * 128 + lane * 4);
    float* np = P.num[seg] + (size_t)d * 128 + lane * 4;
    asm volatile("red.global.add.v4.f32 [%0], {%1, %2, %3, %4};"
                 :: "l"(np), "f"(ex * vv.x), "f"(ex * vv.y),
                    "f"(ex * vv.z), "f"(ex * vv.w) : "memory");
}

// merged normalize + exact GELU for item then user regions
__global__ void gelu_batch(const float* __restrict__ numI, const float* __restrict__ denI,
                           float* __restrict__ outI, int nElemI,
                           const float* __restrict__ numU, const float* __restrict__ denU,
                           float* __restrict__ outU, int nElemU) {
    int i = blockIdx.x * blockDim.x + threadIdx.x;
    const float* num; const float* den; float* out;
    int j;
    if (i < nElemI) { num = numI; den = denI; out = outI; j = i; }
    else if (i < nElemI + nElemU) { num = numU; den = denU; out = outU; j = i - nElemI; }
    else return;
    float dn = den[(size_t)(j >> 7) * 8 + ((j >> 4) & 7)];
    float v = num[j] / (dn + 1e-16f);
    out[j] = 0.5f * v * (1.f + erff(v * 0.70710678118654752f));
}

// ---------------------------------------------------------------------------
extern "C" void kernel_launch(void* const* d_in, const int* in_sizes, int n_in,
                              void* d_out, int out_size) {
    const float* x_user = (const float*)d_in[0];
    const float* x_item = (const float*)d_in[1];
    const float* x_taste = (const float*)d_in[2];
    const float* x_image = (const float*)d_in[3];
    const float* Wk = (const float*)d_in[4];
    const float* bk = (const float*)d_in[5];
    const float* Wq = (const float*)d_in[6];
    const float* bq = (const float*)d_in[7];
    const float* Wv = (const float*)d_in[8];
    const float* bv = (const float*)d_in[9];
    const float* a_rel = (const float*)d_in[10];
    const float* m_rel = (const float*)d_in[11];
    const float* p_rel = (const float*)d_in[12];
    const float* Wo = (const float*)d_in[13];
    const float* bo = (const float*)d_in[14];
    const float* skip = (const float*)d_in[15];
    const int* ti_src = (const int*)d_in[16];
    const int* ti_dst = (const int*)d_in[17];
    const int* im_src = (const int*)d_in[18];
    const int* im_dst = (const int*)d_in[19];
    const int* ub_src = (const int*)d_in[20];
    const int* ub_dst = (const int*)d_in[21];
    const int* bu_src = (const int*)d_in[22];
    const int* bu_dst = (const int*)d_in[23];

    int nUser = in_sizes[0] / HID;
    int nItem = in_sizes[1] / HID;
    int nTaste = in_sizes[2] / HID;
    int nImage = in_sizes[3] / HID;
    int eTI = in_sizes[16], eIM = in_sizes[18], eUB = in_sizes[20], eBU = in_sizes[22];

    float* S = nullptr;
    cudaGetSymbolAddress((void**)&S, g_scratch);
    uint32_t* Wfrag = (uint32_t*)(S + OFF_WFRAG);
    float* Bias = S + OFF_BIAS;

    cudaFuncSetAttribute(mma_gemm_batch,
                         cudaFuncAttributeMaxDynamicSharedMemorySize, GEMM_SMEM);
    cudaFuncSetAttribute(mma_gemm_out,
                         cudaFuncAttributeMaxDynamicSharedMemorySize, GEMM_SMEM);

    // 1) zero accumulators (num_item..den_user contiguous: 9,520,000 floats)
    zero_kernel<<<2048, 256>>>((float4*)(S + OFF_NUM_ITEM), 9520000 / 4);

    // 2) prep weights into fragment layout (+ bias fold)
    prep_kernel<<<(98304 + 1536 + 255) / 256, 256>>>(
        Wk, bk, Wq, bq, Wv, bv, a_rel, m_rel, Wo, bo, Wfrag, Bias);

    // 3) ALL projection GEMMs in one launch
    GemmBatch GB;
    const float* xs[10] = {x_user, x_item, x_user, x_user, x_item,
                           x_item, x_taste, x_taste, x_image, x_image};
    int mats[10]        = {8, 9, 2, 6, 3, 7, 0, 4, 1, 5};
    long long offs[10]  = {OFF_Q_USER, OFF_Q_ITEM, OFF_KR_USER, OFF_VR_USER,
                           OFF_KR_ITEM, OFF_VR_ITEM, OFF_KR_TASTE, OFF_VR_TASTE,
                           OFF_KR_IMAGE, OFF_VR_IMAGE};
    int ns[10] = {nUser, nItem, nUser, nUser, nItem, nItem, nTaste, nTaste, nImage, nImage};
    int maxTiles = 0;
    for (int i = 0; i < 10; i++) {
        GB.X[i] = xs[i];
        GB.W[i] = Wfrag + (size_t)mats[i] * 16384;
        GB.B[i] = Bias + mats[i] * 128;
        GB.Y[i] = S + offs[i];
        GB.N[i] = ns[i];
        int t = (ns[i] + 127) / 128;
        if (t > maxTiles) maxTiles = t;
    }
    mma_gemm_batch<<<dim3(maxTiles, 10), 256, GEMM_SMEM>>>(GB);

    // 4) all edge passes in one launch
    EdgeBatch EB;
    EB.src[0] = ti_src; EB.dst[0] = ti_dst;
    EB.src[1] = im_src; EB.dst[1] = im_dst;
    EB.src[2] = ub_src; EB.dst[2] = ub_dst;
    EB.src[3] = bu_src; EB.dst[3] = bu_dst;
    EB.Q[0] = EB.Q[1] = EB.Q[2] = S + OFF_Q_ITEM;
    EB.Q[3] = S + OFF_Q_USER;
    EB.KR[0] = S + OFF_KR_TASTE; EB.VR[0] = S + OFF_VR_TASTE;
    EB.KR[1] = S + OFF_KR_IMAGE; EB.VR[1] = S + OFF_VR_IMAGE;
    EB.KR[2] = S + OFF_KR_USER;  EB.VR[2] = S + OFF_VR_USER;
    EB.KR[3] = S + OFF_KR_ITEM;  EB.VR[3] = S + OFF_VR_ITEM;
    EB.num[0] = EB.num[1] = EB.num[2] = S + OFF_NUM_ITEM;
    EB.num[3] = S + OFF_NUM_USER;
    EB.den[0] = EB.den[1] = EB.den[2] = S + OFF_DEN_ITEM;
    EB.den[3] = S + OFF_DEN_USER;
    EB.prel = p_rel;
    EB.off[0] = 0;
    EB.off[1] = eTI;
    EB.off[2] = eTI + eIM;
    EB.off[3] = eTI + eIM + eUB;
    EB.off[4] = eTI + eIM + eUB + eBU;
    edge_batch<<<(EB.off[4] + 7) / 8, 256>>>(EB);

    // 5) normalize + GELU (merged)
    int totalG = nItem * HID + nUser * HID;
    gelu_batch<<<(totalG + 255) / 256, 256>>>(
        S + OFF_NUM_ITEM, S + OFF_DEN_ITEM, S + OFF_GEL_ITEM, nItem * HID,
        S + OFF_NUM_USER, S + OFF_DEN_USER, S + OFF_GEL_USER, nUser * HID);

    // 6) output projections with sigmoid-gated residual
    float* out_i = (float*)d_out;
    float* out_u = (float*)d_out + (size_t)nItem * HID;
    mma_gemm_out<<<(nItem + 127) / 128, 256, GEMM_SMEM>>>(
        S + OFF_GEL_ITEM, Wfrag + 10ull * 16384, Bias + 10 * 128, out_i, nItem,
        x_item, skip);
    mma_gemm_out<<<(nUser + 127) / 128, 256, GEMM_SMEM>>>(
        S + OFF_GEL_USER, Wfrag + 11ull * 16384, Bias + 11 * 128, out_u, nUser,
        x_user, skip + 1);

    (void)n_in; (void)out_size;
}

// round 8
// speedup vs baseline: 1.7576x; 1.0900x over previous
#include <cuda_runtime.h>
#include <cuda_bf16.h>
#include <math.h>
#include <stdint.h>

// ---------------------------------------------------------------------------
// MultiModalFusionGAT — mma.sync bf16x3 GEMM + CSR-gather edge phase.
//  * all 10 projection GEMMs in ONE launch (grid.y = matrix)
//  * edge softmax: build CSR (hist/scan/scatter), then warp-per-dst gather
//    with inline normalize + GELU — no atomics on the feature vectors.
// ---------------------------------------------------------------------------

#define HID 128

// scratch layout (floats)
#define OFF_Q_USER   0ll
#define OFF_Q_ITEM   2560000ll
#define OFF_KR_USER  8960000ll
#define OFF_VR_USER  11520000ll
#define OFF_KR_ITEM  14080000ll
#define OFF_VR_ITEM  20480000ll
#define OFF_KR_TASTE 26880000ll
#define OFF_VR_TASTE 33280000ll
#define OFF_KR_IMAGE 39680000ll
#define OFF_VR_IMAGE 46080000ll
#define OFF_CSRBASE  52480000ll   // int-region (reused old num/den space)
#define OFF_GEL_ITEM 62000000ll
#define OFF_GEL_USER 68400000ll
#define OFF_WFRAG    70960000ll   // 12 mats x 16384 u32 (hi 8192 + lo 8192)
#define OFF_BIAS     71156608ll   // 12 x 128 floats
#define SCRATCH_TOTAL 71158144ll

// int offsets inside the CSR region (units: int32)
#define ICSR_I   0          // 600000 entries (item edges, packed src|seg<<16)
#define ICSR_U   600000     // 500000 entries (user edges, src)
#define ISTART_I 1100000    // 50001
#define ISTART_U 1150004    // 20001
#define ICNT_I   1170008    // 50000
#define ICNT_U   1220008    // 20000  (cnt arrays contiguous: 70000 total)

__device__ float g_scratch[SCRATCH_TOTAL];

struct GemmBatch {
    const float* X[10];
    const uint32_t* W[10];
    const float* B[10];
    float* Y[10];
    int N[10];
};

struct EdgeIO {
    const int* src[4];
    const int* dst[4];
    int off[5];
};

struct GatherIO {
    const float* Qi; const float* Qu;
    const float* KR[4]; const float* VR[4];
    const int* csrI; const int* csrU;
    const int* startI; const int* startU;
    float* gelI; float* gelU;
    const float* prel;
    int nI, nU;
};

// ---------------------------------------------------------------------------
__global__ void zero_int4(int4* __restrict__ p, int n4) {
    int i = blockIdx.x * blockDim.x + threadIdx.x;
    if (i < n4) p[i] = make_int4(0, 0, 0, 0);
}

// Folded weight element W[k][n] for matrix m (0-7 fused k/v, 8-9 Wq, 10-11 Wo)
__device__ __forceinline__ float foldW(int m, int k, int n,
        const float* __restrict__ Wk, const float* __restrict__ Wv,
        const float* __restrict__ Wq, const float* __restrict__ Wo,
        const float* __restrict__ a_rel, const float* __restrict__ m_rel) {
    if (m < 8) {
        int r = m & 3;
        int h = n >> 4, e = n & 15;
        int tsrc = (r == 0) ? 2 : (r == 1) ? 3 : (r == 2) ? 0 : 1;
        const float* Wsrc = (m < 4) ? Wk : Wv;
        const float* rel  = (m < 4) ? a_rel : m_rel;
        const float* wrow = Wsrc + tsrc * 16384 + k * 128 + h * 16;
        const float* arow = rel + r * 2048 + h * 256;
        float s = 0.f;
        #pragma unroll
        for (int d = 0; d < 16; d++) s += wrow[d] * arow[d * 16 + e];
        return s;
    } else if (m < 10) {
        return Wq[(m - 8) * 16384 + k * 128 + n];
    }
    return Wo[(m - 10) * 16384 + k * 128 + n];
}

__device__ __forceinline__ uint32_t packbf2(float a, float b) {
    __nv_bfloat16 ha = __float2bfloat16(a), hb = __float2bfloat16(b);
    return (uint32_t)__bfloat16_as_ushort(ha)
         | ((uint32_t)__bfloat16_as_ushort(hb) << 16);
}

__global__ void prep_kernel(const float* __restrict__ Wk, const float* __restrict__ bk,
                            const float* __restrict__ Wq, const float* __restrict__ bq,
                            const float* __restrict__ Wv, const float* __restrict__ bv,
                            const float* __restrict__ a_rel, const float* __restrict__ m_rel,
                            const float* __restrict__ Wo, const float* __restrict__ bo,
                            uint32_t* __restrict__ Wfrag, float* __restrict__ Bias) {
    int idx = blockIdx.x * blockDim.x + threadIdx.x;
    if (idx < 98304) {
        int m = idx >> 13;
        int rest = idx & 8191;
        int kc = rest >> 10;
        int rest2 = rest & 1023;
        int nt = rest2 >> 6;
        int e  = rest2 & 63;
        int lane = e >> 1, r = e & 1;
        int n  = nt * 8 + (lane >> 2);
        int k0 = kc * 16 + (lane & 3) * 2 + r * 8;
        float v0 = foldW(m, k0,     n, Wk, Wv, Wq, Wo, a_rel, m_rel);
        float v1 = foldW(m, k0 + 1, n, Wk, Wv, Wq, Wo, a_rel, m_rel);
        __nv_bfloat16 h0 = __float2bfloat16(v0), h1 = __float2bfloat16(v1);
        float l0 = v0 - __bfloat162float(h0), l1 = v1 - __bfloat162float(h1);
        uint32_t hi = (uint32_t)__bfloat16_as_ushort(h0)
                    | ((uint32_t)__bfloat16_as_ushort(h1) << 16);
        uint32_t lo = packbf2(l0, l1);
        size_t base = (size_t)m * 16384 + ((kc * 16 + nt) * 64 + e);
        Wfrag[base] = hi;
        Wfrag[base + 8192] = lo;
    } else if (idx < 98304 + 1536) {
        int j = idx - 98304;
        int m = j >> 7, n = j & 127;
        float bval;
        if (m < 8) {
            int r = m & 3;
            int h = n >> 4, e2 = n & 15;
            int tsrc = (r == 0) ? 2 : (r == 1) ? 3 : (r == 2) ? 0 : 1;
            const float* bsrc = (m < 4) ? bk : bv;
            const float* rel  = (m < 4) ? a_rel : m_rel;
            const float* brow = bsrc + tsrc * 128 + h * 16;
            const float* arow = rel + r * 2048 + h * 256;
            float sb = 0.f;
            #pragma unroll
            for (int d = 0; d < 16; d++) sb += brow[d] * arow[d * 16 + e2];
            bval = sb;
        } else if (m < 10) {
            bval = bq[(m - 8) * 128 + n];
        } else {
            bval = bo[(m - 10) * 128 + n];
        }
        Bias[m * 128 + n] = bval;
    }
}

// ---------------------------------------------------------------------------
__device__ __forceinline__ void mma16816(float c[4], const uint32_t a[4],
                                         uint32_t b0, uint32_t b1) {
    asm volatile(
        "mma.sync.aligned.m16n8k16.row.col.f32.bf16.bf16.f32 "
        "{%0,%1,%2,%3}, {%4,%5,%6,%7}, {%8,%9}, {%0,%1,%2,%3};"
        : "+f"(c[0]), "+f"(c[1]), "+f"(c[2]), "+f"(c[3])
        : "r"(a[0]), "r"(a[1]), "r"(a[2]), "r"(a[3]), "r"(b0), "r"(b1));
}

__device__ __forceinline__ void split4(const float2& a, const float2& b,
                                       uint32_t& h01, uint32_t& l01,
                                       uint32_t& h23, uint32_t& l23) {
    __nv_bfloat16 ha = __float2bfloat16(a.x), hb = __float2bfloat16(a.y);
    __nv_bfloat16 hc = __float2bfloat16(b.x), hd = __float2bfloat16(b.y);
    h01 = (uint32_t)__bfloat16_as_ushort(ha) | ((uint32_t)__bfloat16_as_ushort(hb) << 16);
    h23 = (uint32_t)__bfloat16_as_ushort(hc) | ((uint32_t)__bfloat16_as_ushort(hd) << 16);
    l01 = packbf2(a.x - __bfloat162float(ha), a.y - __bfloat162float(hb));
    l23 = packbf2(b.x - __bfloat162float(hc), b.y - __bfloat162float(hd));
}

__device__ __forceinline__ void gemm_tile(
        const float* __restrict__ X, const uint32_t* __restrict__ sW,
        const float* __restrict__ Bias, float* __restrict__ Y, int N, int tile0,
        int mode, const float* __restrict__ Res, float g, float omg) {
    int tid = threadIdx.x;
    int warp = tid >> 5, lane = tid & 31;
    int rlo = tile0 + warp * 16 + (lane >> 2);
    int rhi = rlo + 8;
    bool oklo = rlo < N, okhi = rhi < N;
    const float* xlo = X + (size_t)rlo * 128;
    const float* xhi = X + (size_t)rhi * 128;
    int kb = (lane & 3) * 2;

    float C[16][4];
    #pragma unroll
    for (int nt = 0; nt < 16; nt++)
        #pragma unroll
        for (int j = 0; j < 4; j++) C[nt][j] = 0.f;

    float2 z2 = make_float2(0.f, 0.f);
    float2 p00 = oklo ? *(const float2*)(xlo + kb)     : z2;
    float2 p01 = oklo ? *(const float2*)(xlo + kb + 8) : z2;
    float2 p10 = okhi ? *(const float2*)(xhi + kb)     : z2;
    float2 p11 = okhi ? *(const float2*)(xhi + kb + 8) : z2;

    #pragma unroll 1
    for (int kc = 0; kc < 8; kc++) {
        float2 c00 = p00, c01 = p01, c10 = p10, c11 = p11;
        if (kc < 7) {
            int o = (kc + 1) * 16 + kb;
            p00 = oklo ? *(const float2*)(xlo + o)     : z2;
            p01 = oklo ? *(const float2*)(xlo + o + 8) : z2;
            p10 = okhi ? *(const float2*)(xhi + o)     : z2;
            p11 = okhi ? *(const float2*)(xhi + o + 8) : z2;
        }
        uint32_t ahi[4], alo[4];
        split4(c00, c10, ahi[0], alo[0], ahi[1], alo[1]);
        split4(c01, c11, ahi[2], alo[2], ahi[3], alo[3]);
        #pragma unroll
        for (int nt = 0; nt < 16; nt++) {
            uint32_t off = (uint32_t)((kc * 16 + nt) * 64 + lane * 2);
            uint2 bh = *(const uint2*)&sW[off];
            uint2 bl = *(const uint2*)&sW[off + 8192];
            mma16816(C[nt], ahi, bh.x, bh.y);
            mma16816(C[nt], alo, bh.x, bh.y);
            mma16816(C[nt], ahi, bl.x, bl.y);
        }
    }

    #pragma unroll
    for (int nt = 0; nt < 16; nt++) {
        int col = nt * 8 + kb;
        float2 b = *(const float2*)(Bias + col);
        if (oklo) {
            float2 o = make_float2(C[nt][0] + b.x, C[nt][1] + b.y);
            if (mode == 1) {
                float2 rv = *(const float2*)(Res + (size_t)rlo * 128 + col);
                o.x = g * o.x + omg * rv.x;
                o.y = g * o.y + omg * rv.y;
            }
            *(float2*)(Y + (size_t)rlo * 128 + col) = o;
        }
        if (okhi) {
            float2 o = make_float2(C[nt][2] + b.x, C[nt][3] + b.y);
            if (mode == 1) {
                float2 rv = *(const float2*)(Res + (size_t)rhi * 128 + col);
                o.x = g * o.x + omg * rv.x;
                o.y = g * o.y + omg * rv.y;
            }
            *(float2*)(Y + (size_t)rhi * 128 + col) = o;
        }
    }
}

#define GEMM_SMEM 65536

__global__ void __launch_bounds__(256) mma_gemm_batch(GemmBatch P) {
    int m = blockIdx.y;
    int N = P.N[m];
    int tile0 = blockIdx.x * 128;
    if (tile0 >= N) return;
    extern __shared__ uint32_t sW[];
    {
        const uint4* src = (const uint4*)P.W[m];
        uint4* dst = (uint4*)sW;
        int tid = threadIdx.x;
        #pragma unroll
        for (int i = 0; i < 16; i++) dst[tid + i * 256] = src[tid + i * 256];
    }
    __syncthreads();
    gemm_tile(P.X[m], sW, P.B[m], P.Y[m], N, tile0, 0, nullptr, 1.f, 0.f);
}

__global__ void __launch_bounds__(256) mma_gemm_out(
        const float* __restrict__ X, const uint32_t* __restrict__ Wfrag,
        const float* __restrict__ Bias, float* __restrict__ Y, int N,
        const float* __restrict__ Res, const float* __restrict__ SkipP) {
    extern __shared__ uint32_t sW[];
    {
        const uint4* src = (const uint4*)Wfrag;
        uint4* dst = (uint4*)sW;
        int tid = threadIdx.x;
        #pragma unroll
        for (int i = 0; i < 16; i++) dst[tid + i * 256] = src[tid + i * 256];
    }
    __syncthreads();
    float g = 1.f / (1.f + expf(-SkipP[0]));
    gemm_tile(X, sW, Bias, Y, N, blockIdx.x * 128, 1, Res, g, 1.f - g);
}

// ---------------------------------------------------------------------------
// CSR build
__global__ void hist_kernel(EdgeIO E, int* __restrict__ cntI, int* __restrict__ cntU) {
    int g = blockIdx.x * 256 + threadIdx.x;
    if (g >= E.off[4]) return;
    int seg = (g >= E.off[1]) + (g >= E.off[2]) + (g >= E.off[3]);
    int e = g - E.off[seg];
    int d = E.dst[seg][e];
    atomicAdd((seg < 3) ? (cntI + d) : (cntU + d), 1);
}

// block-wide exclusive scan; grid.x=2 (0: item, 1: user). Resets cnt to 0.
__global__ void scan_kernel(int* __restrict__ cntI, int* __restrict__ startI, int nI,
                            int* __restrict__ cntU, int* __restrict__ startU, int nU) {
    int* cnt   = blockIdx.x ? cntU : cntI;
    int* start = blockIdx.x ? startU : startI;
    int n      = blockIdx.x ? nU : nI;
    __shared__ int wsum[32];
    __shared__ int s_carry;
    int tid = threadIdx.x, lane = tid & 31, wid = tid >> 5;
    if (tid == 0) s_carry = 0;
    __syncthreads();
    for (int base = 0; base < n; base += 1024) {
        int i = base + tid;
        int v = (i < n) ? cnt[i] : 0;
        if (i < n) cnt[i] = 0;        // becomes the scatter cursor
        int incl = v;
        #pragma unroll
        for (int o = 1; o < 32; o <<= 1) {
            int t = __shfl_up_sync(0xFFFFFFFFu, incl, o);
            if (lane >= o) incl += t;
        }
        if (lane == 31) wsum[wid] = incl;
        __syncthreads();
        if (wid == 0) {
            int w = wsum[lane];
            int wi = w;
            #pragma unroll
            for (int o = 1; o < 32; o <<= 1) {
                int t = __shfl_up_sync(0xFFFFFFFFu, wi, o);
                if (lane >= o) wi += t;
            }
            wsum[lane] = wi - w;
        }
        __syncthreads();
        int excl = incl - v + wsum[wid] + s_carry;
        if (i < n) start[i] = excl;
        __syncthreads();
        if (tid == 1023) s_carry = excl + v;
        __syncthreads();
    }
    if (tid == 0) start[n] = s_carry;
}

__global__ void scatter_kernel(EdgeIO E,
                               const int* __restrict__ startI, const int* __restrict__ startU,
                               int* __restrict__ cntI, int* __restrict__ cntU,
                               int* __restrict__ csrI, int* __restrict__ csrU) {
    int g = blockIdx.x * 256 + threadIdx.x;
    if (g >= E.off[4]) return;
    int seg = (g >= E.off[1]) + (g >= E.off[2]) + (g >= E.off[3]);
    int e = g - E.off[seg];
    int d = E.dst[seg][e];
    int s = E.src[seg][e];
    if (seg < 3) {
        int pos = startI[d] + atomicAdd(cntI + d, 1);
        csrI[pos] = s | (seg << 16);
    } else {
        int pos = startU[d] + atomicAdd(cntU + d, 1);
        csrU[pos] = s;
    }
}

// warp-per-dst gather: softmax-weighted aggregate + inline GELU
__global__ void __launch_bounds__(256) gather_kernel(GatherIO P) {
    int w = blockIdx.x * 8 + (threadIdx.x >> 5);
    int lane = threadIdx.x & 31;
    int h = lane >> 2;
    bool item = w < P.nI;
    int d = item ? w : w - P.nI;
    if (!item && d >= P.nU) return;

    const float* q = (item ? P.Qi : P.Qu) + (size_t)d * 128;
    float4 qv = *(const float4*)(q + lane * 4);
    const int* csr = item ? P.csrI : P.csrU;
    int js = item ? P.startI[d] : P.startU[d];
    int je = item ? P.startI[d + 1] : P.startU[d + 1];
    float p0, p1, p2;
    if (item) { p0 = P.prel[h]; p1 = P.prel[8 + h]; p2 = P.prel[16 + h]; }
    else      { p0 = p1 = p2 = P.prel[24 + h]; }

    float4 acc = make_float4(0.f, 0.f, 0.f, 0.f);
    float den = 0.f;
    for (int j = js; j < je; j++) {
        int e = csr[j];
        int s = e & 0xFFFF;
        int seg = item ? (e >> 16) : 3;
        const float* kr = P.KR[seg] + (size_t)s * 128;
        const float* vr = P.VR[seg] + (size_t)s * 128;
        float4 kv = *(const float4*)(kr + lane * 4);
        float part = qv.x * kv.x + qv.y * kv.y + qv.z * kv.z + qv.w * kv.w;
        part += __shfl_xor_sync(0xFFFFFFFFu, part, 1);
        part += __shfl_xor_sync(0xFFFFFFFFu, part, 2);
        float p = item ? ((seg == 0) ? p0 : ((seg == 1) ? p1 : p2)) : p0;
        float ex = __expf(part * p * 0.25f);
        float4 vv = *(const float4*)(vr + lane * 4);
        den += ex;
        acc.x += ex * vv.x; acc.y += ex * vv.y;
        acc.z += ex * vv.z; acc.w += ex * vv.w;
    }
    float inv = 1.f / (den + 1e-16f);
    const float RS2 = 0.70710678118654752f;
    float4 o;
    float v;
    v = acc.x * inv; o.x = 0.5f * v * (1.f + erff(v * RS2));
    v = acc.y * inv; o.y = 0.5f * v * (1.f + erff(v * RS2));
    v = acc.z * inv; o.z = 0.5f * v * (1.f + erff(v * RS2));
    v = acc.w * inv; o.w = 0.5f * v * (1.f + erff(v * RS2));
    float* out = (item ? P.gelI : P.gelU) + (size_t)d * 128 + lane * 4;
    *(float4*)out = o;
}

// ---------------------------------------------------------------------------
extern "C" void kernel_launch(void* const* d_in, const int* in_sizes, int n_in,
                              void* d_out, int out_size) {
    const float* x_user = (const float*)d_in[0];
    const float* x_item = (const float*)d_in[1];
    const float* x_taste = (const float*)d_in[2];
    const float* x_image = (const float*)d_in[3];
    const float* Wk = (const float*)d_in[4];
    const float* bk = (const float*)d_in[5];
    const float* Wq = (const float*)d_in[6];
    const float* bq = (const float*)d_in[7];
    const float* Wv = (const float*)d_in[8];
    const float* bv = (const float*)d_in[9];
    const float* a_rel = (const float*)d_in[10];
    const float* m_rel = (const float*)d_in[11];
    const float* p_rel = (const float*)d_in[12];
    const float* Wo = (const float*)d_in[13];
    const float* bo = (const float*)d_in[14];
    const float* skip = (const float*)d_in[15];
    const int* ti_src = (const int*)d_in[16];
    const int* ti_dst = (const int*)d_in[17];
    const int* im_src = (const int*)d_in[18];
    const int* im_dst = (const int*)d_in[19];
    const int* ub_src = (const int*)d_in[20];
    const int* ub_dst = (const int*)d_in[21];
    const int* bu_src = (const int*)d_in[22];
    const int* bu_dst = (const int*)d_in[23];

    int nUser = in_sizes[0] / HID;
    int nItem = in_sizes[1] / HID;
    int nTaste = in_sizes[2] / HID;
    int nImage = in_sizes[3] / HID;
    int eTI = in_sizes[16], eIM = in_sizes[18], eUB = in_sizes[20], eBU = in_sizes[22];

    float* S = nullptr;
    cudaGetSymbolAddress((void**)&S, g_scratch);
    uint32_t* Wfrag = (uint32_t*)(S + OFF_WFRAG);
    float* Bias = S + OFF_BIAS;
    int* I = (int*)(S + OFF_CSRBASE);

    cudaFuncSetAttribute(mma_gemm_batch,
                         cudaFuncAttributeMaxDynamicSharedMemorySize, GEMM_SMEM);
    cudaFuncSetAttribute(mma_gemm_out,
                         cudaFuncAttributeMaxDynamicSharedMemorySize, GEMM_SMEM);

    // 1) prep weights into fragment layout (+ bias fold)
    prep_kernel<<<(98304 + 1536 + 255) / 256, 256>>>(
        Wk, bk, Wq, bq, Wv, bv, a_rel, m_rel, Wo, bo, Wfrag, Bias);

    // 2) zero CSR counters (cntI|cntU contiguous: 70000 ints)
    zero_int4<<<(17500 + 255) / 256, 256>>>((int4*)(I + ICNT_I), 17500);

    // 3) ALL projection GEMMs in one launch
    GemmBatch GB;
    const float* xs[10] = {x_user, x_item, x_user, x_user, x_item,
                           x_item, x_taste, x_taste, x_image, x_image};
    int mats[10]        = {8, 9, 2, 6, 3, 7, 0, 4, 1, 5};
    long long offs[10]  = {OFF_Q_USER, OFF_Q_ITEM, OFF_KR_USER, OFF_VR_USER,
                           OFF_KR_ITEM, OFF_VR_ITEM, OFF_KR_TASTE, OFF_VR_TASTE,
                           OFF_KR_IMAGE, OFF_VR_IMAGE};
    int ns[10] = {nUser, nItem, nUser, nUser, nItem, nItem, nTaste, nTaste, nImage, nImage};
    int maxTiles = 0;
    for (int i = 0; i < 10; i++) {
        GB.X[i] = xs[i];
        GB.W[i] = Wfrag + (size_t)mats[i] * 16384;
        GB.B[i] = Bias + mats[i] * 128;
        GB.Y[i] = S + offs[i];
        GB.N[i] = ns[i];
        int t = (ns[i] + 127) / 128;
        if (t > maxTiles) maxTiles = t;
    }
    mma_gemm_batch<<<dim3(maxTiles, 10), 256, GEMM_SMEM>>>(GB);

    // 4) CSR build: hist -> scan -> scatter
    EdgeIO E;
    E.src[0] = ti_src; E.dst[0] = ti_dst;
    E.src[1] = im_src; E.dst[1] = im_dst;
    E.src[2] = ub_src; E.dst[2] = ub_dst;
    E.src[3] = bu_src; E.dst[3] = bu_dst;
    E.off[0] = 0;
    E.off[1] = eTI;
    E.off[2] = eTI + eIM;
    E.off[3] = eTI + eIM + eUB;
    E.off[4] = eTI + eIM + eUB + eBU;
    int eTotal = E.off[4];
    hist_kernel<<<(eTotal + 255) / 256, 256>>>(E, I + ICNT_I, I + ICNT_U);
    scan_kernel<<<2, 1024>>>(I + ICNT_I, I + ISTART_I, nItem,
                             I + ICNT_U, I + ISTART_U, nUser);
    scatter_kernel<<<(eTotal + 255) / 256, 256>>>(E, I + ISTART_I, I + ISTART_U,
                                                  I + ICNT_I, I + ICNT_U,
                                                  I + ICSR_I, I + ICSR_U);

    // 5) gather: softmax aggregate + GELU, one warp per dst node
    GatherIO G;
    G.Qi = S + OFF_Q_ITEM;
    G.Qu = S + OFF_Q_USER;
    G.KR[0] = S + OFF_KR_TASTE; G.VR[0] = S + OFF_VR_TASTE;
    G.KR[1] = S + OFF_KR_IMAGE; G.VR[1] = S + OFF_VR_IMAGE;
    G.KR[2] = S + OFF_KR_USER;  G.VR[2] = S + OFF_VR_USER;
    G.KR[3] = S + OFF_KR_ITEM;  G.VR[3] = S + OFF_VR_ITEM;
    G.csrI = I + ICSR_I;   G.csrU = I + ICSR_U;
    G.startI = I + ISTART_I; G.startU = I + ISTART_U;
    G.gelI = S + OFF_GEL_ITEM; G.gelU = S + OFF_GEL_USER;
    G.prel = p_rel;
    G.nI = nItem; G.nU = nUser;
    int warps = nItem + nUser;
    gather_kernel<<<(warps + 7) / 8, 256>>>(G);

    // 6) output projections with sigmoid-gated residual
    float* out_i = (float*)d_out;
    float* out_u = (float*)d_out + (size_t)nItem * HID;
    mma_gemm_out<<<(nItem + 127) / 128, 256, GEMM_SMEM>>>(
        S + OFF_GEL_ITEM, Wfrag + 10ull * 16384, Bias + 10 * 128, out_i, nItem,
        x_item, skip);
    mma_gemm_out<<<(nUser + 127) / 128, 256, GEMM_SMEM>>>(
        S + OFF_GEL_USER, Wfrag + 11ull * 16384, Bias + 11 * 128, out_u, nUser,
        x_user, skip + 1);

    (void)n_in; (void)out_size;
}

// round 10
// speedup vs baseline: 1.7762x; 1.0105x over previous
#include <cuda_runtime.h>
#include <cuda_bf16.h>
#include <math.h>
#include <stdint.h>

// ---------------------------------------------------------------------------
// MultiModalFusionGAT — mma.sync bf16x3 GEMM + CSR-gather edge phase.
//  * KR/VR stored interleaved per node (one 1KB row) for gather locality
//  * gather loop unrolled x2 for memory-level parallelism
// ---------------------------------------------------------------------------

#define HID 128

// scratch layout (floats)
#define OFF_Q_USER   0ll
#define OFF_Q_ITEM   2560000ll
#define OFF_KV_USER  8960000ll    // 20000 * 256 (kr | vr interleaved)
#define OFF_KV_ITEM  14080000ll   // 50000 * 256
#define OFF_KV_TASTE 26880000ll   // 50000 * 256
#define OFF_KV_IMAGE 39680000ll   // 50000 * 256
#define OFF_CSRBASE  52480000ll   // int region
#define OFF_GEL_ITEM 62000000ll
#define OFF_GEL_USER 68400000ll
#define OFF_WFRAG    70960000ll   // 12 mats x 16384 u32 (hi 8192 + lo 8192)
#define OFF_BIAS     71156608ll   // 12 x 128 floats
#define SCRATCH_TOTAL 71158144ll

// int offsets inside the CSR region (units: int32)
#define ICSR_I   0          // 600000 entries (item edges, packed src|seg<<16)
#define ICSR_U   600000     // 500000 entries (user edges, src)
#define ISTART_I 1100000    // 50001
#define ISTART_U 1150004    // 20001
#define ICNT_I   1170008    // 50000
#define ICNT_U   1220008    // 20000  (cnt arrays contiguous: 70000 total)

__device__ float g_scratch[SCRATCH_TOTAL];

struct GemmBatch {
    const float* X[10];
    const uint32_t* W[10];
    const float* B[10];
    float* Y[10];
    int N[10];
    int YS[10];   // output row stride (floats)
};

struct EdgeIO {
    const int* src[4];
    const int* dst[4];
    int off[5];
};

struct GatherIO {
    const float* Qi; const float* Qu;
    const float* KV[4];           // interleaved kr|vr, 256 floats/node
    const int* csrI; const int* csrU;
    const int* startI; const int* startU;
    float* gelI; float* gelU;
    const float* prel;
    int nI, nU;
};

// ---------------------------------------------------------------------------
__global__ void zero_int4(int4* __restrict__ p, int n4) {
    int i = blockIdx.x * blockDim.x + threadIdx.x;
    if (i < n4) p[i] = make_int4(0, 0, 0, 0);
}

__device__ __forceinline__ float foldW(int m, int k, int n,
        const float* __restrict__ Wk, const float* __restrict__ Wv,
        const float* __restrict__ Wq, const float* __restrict__ Wo,
        const float* __restrict__ a_rel, const float* __restrict__ m_rel) {
    if (m < 8) {
        int r = m & 3;
        int h = n >> 4, e = n & 15;
        int tsrc = (r == 0) ? 2 : (r == 1) ? 3 : (r == 2) ? 0 : 1;
        const float* Wsrc = (m < 4) ? Wk : Wv;
        const float* rel  = (m < 4) ? a_rel : m_rel;
        const float* wrow = Wsrc + tsrc * 16384 + k * 128 + h * 16;
        const float* arow = rel + r * 2048 + h * 256;
        float s = 0.f;
        #pragma unroll
        for (int d = 0; d < 16; d++) s += wrow[d] * arow[d * 16 + e];
        return s;
    } else if (m < 10) {
        return Wq[(m - 8) * 16384 + k * 128 + n];
    }
    return Wo[(m - 10) * 16384 + k * 128 + n];
}

__device__ __forceinline__ uint32_t packbf2(float a, float b) {
    __nv_bfloat16 ha = __float2bfloat16(a), hb = __float2bfloat16(b);
    return (uint32_t)__bfloat16_as_ushort(ha)
         | ((uint32_t)__bfloat16_as_ushort(hb) << 16);
}

__global__ void prep_kernel(const float* __restrict__ Wk, const float* __restrict__ bk,
                            const float* __restrict__ Wq, const float* __restrict__ bq,
                            const float* __restrict__ Wv, const float* __restrict__ bv,
                            const float* __restrict__ a_rel, const float* __restrict__ m_rel,
                            const float* __restrict__ Wo, const float* __restrict__ bo,
                            uint32_t* __restrict__ Wfrag, float* __restrict__ Bias) {
    int idx = blockIdx.x * blockDim.x + threadIdx.x;
    if (idx < 98304) {
        int m = idx >> 13;
        int rest = idx & 8191;
        int kc = rest >> 10;
        int rest2 = rest & 1023;
        int nt = rest2 >> 6;
        int e  = rest2 & 63;
        int lane = e >> 1, r = e & 1;
        int n  = nt * 8 + (lane >> 2);
        int k0 = kc * 16 + (lane & 3) * 2 + r * 8;
        float v0 = foldW(m, k0,     n, Wk, Wv, Wq, Wo, a_rel, m_rel);
        float v1 = foldW(m, k0 + 1, n, Wk, Wv, Wq, Wo, a_rel, m_rel);
        __nv_bfloat16 h0 = __float2bfloat16(v0), h1 = __float2bfloat16(v1);
        float l0 = v0 - __bfloat162float(h0), l1 = v1 - __bfloat162float(h1);
        uint32_t hi = (uint32_t)__bfloat16_as_ushort(h0)
                    | ((uint32_t)__bfloat16_as_ushort(h1) << 16);
        uint32_t lo = packbf2(l0, l1);
        size_t base = (size_t)m * 16384 + ((kc * 16 + nt) * 64 + e);
        Wfrag[base] = hi;
        Wfrag[base + 8192] = lo;
    } else if (idx < 98304 + 1536) {
        int j = idx - 98304;
        int m = j >> 7, n = j & 127;
        float bval;
        if (m < 8) {
            int r = m & 3;
            int h = n >> 4, e2 = n & 15;
            int tsrc = (r == 0) ? 2 : (r == 1) ? 3 : (r == 2) ? 0 : 1;
            const float* bsrc = (m < 4) ? bk : bv;
            const float* rel  = (m < 4) ? a_rel : m_rel;
            const float* brow = bsrc + tsrc * 128 + h * 16;
            const float* arow = rel + r * 2048 + h * 256;
            float sb = 0.f;
            #pragma unroll
            for (int d = 0; d < 16; d++) sb += brow[d] * arow[d * 16 + e2];
            bval = sb;
        } else if (m < 10) {
            bval = bq[(m - 8) * 128 + n];
        } else {
            bval = bo[(m - 10) * 128 + n];
        }
        Bias[m * 128 + n] = bval;
    }
}

// ---------------------------------------------------------------------------
__device__ __forceinline__ void mma16816(float c[4], const uint32_t a[4],
                                         uint32_t b0, uint32_t b1) {
    asm volatile(
        "mma.sync.aligned.m16n8k16.row.col.f32.bf16.bf16.f32 "
        "{%0,%1,%2,%3}, {%4,%5,%6,%7}, {%8,%9}, {%0,%1,%2,%3};"
        : "+f"(c[0]), "+f"(c[1]), "+f"(c[2]), "+f"(c[3])
        : "r"(a[0]), "r"(a[1]), "r"(a[2]), "r"(a[3]), "r"(b0), "r"(b1));
}

__device__ __forceinline__ void split4(const float2& a, const float2& b,
                                       uint32_t& h01, uint32_t& l01,
                                       uint32_t& h23, uint32_t& l23) {
    __nv_bfloat16 ha = __float2bfloat16(a.x), hb = __float2bfloat16(a.y);
    __nv_bfloat16 hc = __float2bfloat16(b.x), hd = __float2bfloat16(b.y);
    h01 = (uint32_t)__bfloat16_as_ushort(ha) | ((uint32_t)__bfloat16_as_ushort(hb) << 16);
    h23 = (uint32_t)__bfloat16_as_ushort(hc) | ((uint32_t)__bfloat16_as_ushort(hd) << 16);
    l01 = packbf2(a.x - __bfloat162float(ha), a.y - __bfloat162float(hb));
    l23 = packbf2(b.x - __bfloat162float(hc), b.y - __bfloat162float(hd));
}

// Core 128x128 tile GEMM (bf16x3), pipelined kc loop. ystride = output row
// stride in floats (256 for interleaved KV targets, 128 otherwise).
__device__ __forceinline__ void gemm_tile(
        const float* __restrict__ X, const uint32_t* __restrict__ sW,
        const float* __restrict__ Bias, float* __restrict__ Y, int N, int tile0,
        int ystride, int mode, const float* __restrict__ Res, float g, float omg) {
    int tid = threadIdx.x;
    int warp = tid >> 5, lane = tid & 31;
    int rlo = tile0 + warp * 16 + (lane >> 2);
    int rhi = rlo + 8;
    bool oklo = rlo < N, okhi = rhi < N;
    const float* xlo = X + (size_t)rlo * 128;
    const float* xhi = X + (size_t)rhi * 128;
    int kb = (lane & 3) * 2;

    float C[16][4];
    #pragma unroll
    for (int nt = 0; nt < 16; nt++)
        #pragma unroll
        for (int j = 0; j < 4; j++) C[nt][j] = 0.f;

    float2 z2 = make_float2(0.f, 0.f);
    float2 p00 = oklo ? *(const float2*)(xlo + kb)     : z2;
    float2 p01 = oklo ? *(const float2*)(xlo + kb + 8) : z2;
    float2 p10 = okhi ? *(const float2*)(xhi + kb)     : z2;
    float2 p11 = okhi ? *(const float2*)(xhi + kb + 8) : z2;

    #pragma unroll 1
    for (int kc = 0; kc < 8; kc++) {
        float2 c00 = p00, c01 = p01, c10 = p10, c11 = p11;
        if (kc < 7) {
            int o = (kc + 1) * 16 + kb;
            p00 = oklo ? *(const float2*)(xlo + o)     : z2;
            p01 = oklo ? *(const float2*)(xlo + o + 8) : z2;
            p10 = okhi ? *(const float2*)(xhi + o)     : z2;
            p11 = okhi ? *(const float2*)(xhi + o + 8) : z2;
        }
        uint32_t ahi[4], alo[4];
        split4(c00, c10, ahi[0], alo[0], ahi[1], alo[1]);
        split4(c01, c11, ahi[2], alo[2], ahi[3], alo[3]);
        #pragma unroll
        for (int nt = 0; nt < 16; nt++) {
            uint32_t off = (uint32_t)((kc * 16 + nt) * 64 + lane * 2);
            uint2 bh = *(const uint2*)&sW[off];
            uint2 bl = *(const uint2*)&sW[off + 8192];
            mma16816(C[nt], ahi, bh.x, bh.y);
            mma16816(C[nt], alo, bh.x, bh.y);
            mma16816(C[nt], ahi, bl.x, bl.y);
        }
    }

    #pragma unroll
    for (int nt = 0; nt < 16; nt++) {
        int col = nt * 8 + kb;
        float2 b = *(const float2*)(Bias + col);
        if (oklo) {
            float2 o = make_float2(C[nt][0] + b.x, C[nt][1] + b.y);
            if (mode == 1) {
                float2 rv = *(const float2*)(Res + (size_t)rlo * 128 + col);
                o.x = g * o.x + omg * rv.x;
                o.y = g * o.y + omg * rv.y;
            }
            *(float2*)(Y + (size_t)rlo * ystride + col) = o;
        }
        if (okhi) {
            float2 o = make_float2(C[nt][2] + b.x, C[nt][3] + b.y);
            if (mode == 1) {
                float2 rv = *(const float2*)(Res + (size_t)rhi * 128 + col);
                o.x = g * o.x + omg * rv.x;
                o.y = g * o.y + omg * rv.y;
            }
            *(float2*)(Y + (size_t)rhi * ystride + col) = o;
        }
    }
}

#define GEMM_SMEM 65536

__global__ void __launch_bounds__(256) mma_gemm_batch(GemmBatch P) {
    int m = blockIdx.y;
    int N = P.N[m];
    int tile0 = blockIdx.x * 128;
    if (tile0 >= N) return;
    extern __shared__ uint32_t sW[];
    {
        const uint4* src = (const uint4*)P.W[m];
        uint4* dst = (uint4*)sW;
        int tid = threadIdx.x;
        #pragma unroll
        for (int i = 0; i < 16; i++) dst[tid + i * 256] = src[tid + i * 256];
    }
    __syncthreads();
    gemm_tile(P.X[m], sW, P.B[m], P.Y[m], N, tile0, P.YS[m], 0, nullptr, 1.f, 0.f);
}

__global__ void __launch_bounds__(256) mma_gemm_out(
        const float* __restrict__ X, const uint32_t* __restrict__ Wfrag,
        const float* __restrict__ Bias, float* __restrict__ Y, int N,
        const float* __restrict__ Res, const float* __restrict__ SkipP) {
    extern __shared__ uint32_t sW[];
    {
        const uint4* src = (const uint4*)Wfrag;
        uint4* dst = (uint4*)sW;
        int tid = threadIdx.x;
        #pragma unroll
        for (int i = 0; i < 16; i++) dst[tid + i * 256] = src[tid + i * 256];
    }
    __syncthreads();
    float g = 1.f / (1.f + expf(-SkipP[0]));
    gemm_tile(X, sW, Bias, Y, N, blockIdx.x * 128, 128, 1, Res, g, 1.f - g);
}

// ---------------------------------------------------------------------------
// CSR build
__global__ void hist_kernel(EdgeIO E, int* __restrict__ cntI, int* __restrict__ cntU) {
    int g = blockIdx.x * 256 + threadIdx.x;
    if (g >= E.off[4]) return;
    int seg = (g >= E.off[1]) + (g >= E.off[2]) + (g >= E.off[3]);
    int e = g - E.off[seg];
    int d = E.dst[seg][e];
    atomicAdd((seg < 3) ? (cntI + d) : (cntU + d), 1);
}

__global__ void scan_kernel(int* __restrict__ cntI, int* __restrict__ startI, int nI,
                            int* __restrict__ cntU, int* __restrict__ startU, int nU) {
    int* cnt   = blockIdx.x ? cntU : cntI;
    int* start = blockIdx.x ? startU : startI;
    int n      = blockIdx.x ? nU : nI;
    __shared__ int wsum[32];
    __shared__ int s_carry;
    int tid = threadIdx.x, lane = tid & 31, wid = tid >> 5;
    if (tid == 0) s_carry = 0;
    __syncthreads();
    for (int base = 0; base < n; base += 1024) {
        int i = base + tid;
        int v = (i < n) ? cnt[i] : 0;
        if (i < n) cnt[i] = 0;
        int incl = v;
        #pragma unroll
        for (int o = 1; o < 32; o <<= 1) {
            int t = __shfl_up_sync(0xFFFFFFFFu, incl, o);
            if (lane >= o) incl += t;
        }
        if (lane == 31) wsum[wid] = incl;
        __syncthreads();
        if (wid == 0) {
            int w = wsum[lane];
            int wi = w;
            #pragma unroll
            for (int o = 1; o < 32; o <<= 1) {
                int t = __shfl_up_sync(0xFFFFFFFFu, wi, o);
                if (lane >= o) wi += t;
            }
            wsum[lane] = wi - w;
        }
        __syncthreads();
        int excl = incl - v + wsum[wid] + s_carry;
        if (i < n) start[i] = excl;
        __syncthreads();
        if (tid == 1023) s_carry = excl + v;
        __syncthreads();
    }
    if (tid == 0) start[n] = s_carry;
}

__global__ void scatter_kernel(EdgeIO E,
                               const int* __restrict__ startI, const int* __restrict__ startU,
                               int* __restrict__ cntI, int* __restrict__ cntU,
                               int* __restrict__ csrI, int* __restrict__ csrU) {
    int g = blockIdx.x * 256 + threadIdx.x;
    if (g >= E.off[4]) return;
    int seg = (g >= E.off[1]) + (g >= E.off[2]) + (g >= E.off[3]);
    int e = g - E.off[seg];
    int d = E.dst[seg][e];
    int s = E.src[seg][e];
    if (seg < 3) {
        int pos = startI[d] + atomicAdd(cntI + d, 1);
        csrI[pos] = s | (seg << 16);
    } else {
        int pos = startU[d] + atomicAdd(cntU + d, 1);
        csrU[pos] = s;
    }
}

// warp-per-dst gather, unrolled x2: softmax aggregate + inline GELU
__global__ void __launch_bounds__(256) gather_kernel(GatherIO P) {
    int w = blockIdx.x * 8 + (threadIdx.x >> 5);
    int lane = threadIdx.x & 31;
    int h = lane >> 2;
    bool item = w < P.nI;
    int d = item ? w : w - P.nI;
    if (!item && d >= P.nU) return;

    const float* q = (item ? P.Qi : P.Qu) + (size_t)d * 128;
    float4 qv = *(const float4*)(q + lane * 4);
    const int* csr = item ? P.csrI : P.csrU;
    int js = item ? P.startI[d] : P.startU[d];
    int je = item ? P.startI[d + 1] : P.startU[d + 1];
    float p0, p1, p2;
    if (item) { p0 = P.prel[h]; p1 = P.prel[8 + h]; p2 = P.prel[16 + h]; }
    else      { p0 = p1 = p2 = P.prel[24 + h]; }

    float4 acc = make_float4(0.f, 0.f, 0.f, 0.f);
    float den = 0.f;
    int j = js;
    for (; j + 1 < je; j += 2) {
        int e0 = csr[j], e1 = csr[j + 1];
        int s0 = e0 & 0xFFFF, s1 = e1 & 0xFFFF;
        int g0 = item ? (e0 >> 16) : 3, g1 = item ? (e1 >> 16) : 3;
        const float* kv0b = P.KV[g0] + (size_t)s0 * 256;
        const float* kv1b = P.KV[g1] + (size_t)s1 * 256;
        // issue all 4 loads before either reduction chain
        float4 k0 = *(const float4*)(kv0b + lane * 4);
        float4 v0 = *(const float4*)(kv0b + 128 + lane * 4);
        float4 k1 = *(const float4*)(kv1b + lane * 4);
        float4 v1 = *(const float4*)(kv1b + 128 + lane * 4);
        float pa = qv.x * k0.x + qv.y * k0.y + qv.z * k0.z + qv.w * k0.w;
        float pb = qv.x * k1.x + qv.y * k1.y + qv.z * k1.z + qv.w * k1.w;
        pa += __shfl_xor_sync(0xFFFFFFFFu, pa, 1);
        pb += __shfl_xor_sync(0xFFFFFFFFu, pb, 1);
        pa += __shfl_xor_sync(0xFFFFFFFFu, pa, 2);
        pb += __shfl_xor_sync(0xFFFFFFFFu, pb, 2);
        float pr0 = item ? ((g0 == 0) ? p0 : ((g0 == 1) ? p1 : p2)) : p0;
        float pr1 = item ? ((g1 == 0) ? p0 : ((g1 == 1) ? p1 : p2)) : p0;
        float ex0 = __expf(pa * pr0 * 0.25f);
        float ex1 = __expf(pb * pr1 * 0.25f);
        den += ex0 + ex1;
        acc.x += ex0 * v0.x + ex1 * v1.x;
        acc.y += ex0 * v0.y + ex1 * v1.y;
        acc.z += ex0 * v0.z + ex1 * v1.z;
        acc.w += ex0 * v0.w + ex1 * v1.w;
    }
    if (j < je) {
        int e0 = csr[j];
        int s0 = e0 & 0xFFFF;
        int g0 = item ? (e0 >> 16) : 3;
        const float* kv0b = P.KV[g0] + (size_t)s0 * 256;
        float4 k0 = *(const float4*)(kv0b + lane * 4);
        float4 v0 = *(const float4*)(kv0b + 128 + lane * 4);
        float pa = qv.x * k0.x + qv.y * k0.y + qv.z * k0.z + qv.w * k0.w;
        pa += __shfl_xor_sync(0xFFFFFFFFu, pa, 1);
        pa += __shfl_xor_sync(0xFFFFFFFFu, pa, 2);
        float pr0 = item ? ((g0 == 0) ? p0 : ((g0 == 1) ? p1 : p2)) : p0;
        float ex0 = __expf(pa * pr0 * 0.25f);
        den += ex0;
        acc.x += ex0 * v0.x; acc.y += ex0 * v0.y;
        acc.z += ex0 * v0.z; acc.w += ex0 * v0.w;
    }
    float inv = 1.f / (den + 1e-16f);
    const float RS2 = 0.70710678118654752f;
    float4 o;
    float v;
    v = acc.x * inv; o.x = 0.5f * v * (1.f + erff(v * RS2));
    v = acc.y * inv; o.y = 0.5f * v * (1.f + erff(v * RS2));
    v = acc.z * inv; o.z = 0.5f * v * (1.f + erff(v * RS2));
    v = acc.w * inv; o.w = 0.5f * v * (1.f + erff(v * RS2));
    float* out = (item ? P.gelI : P.gelU) + (size_t)d * 128 + lane * 4;
    *(float4*)out = o;
}

// ---------------------------------------------------------------------------
extern "C" void kernel_launch(void* const* d_in, const int* in_sizes, int n_in,
                              void* d_out, int out_size) {
    const float* x_user = (const float*)d_in[0];
    const float* x_item = (const float*)d_in[1];
    const float* x_taste = (const float*)d_in[2];
    const float* x_image = (const float*)d_in[3];
    const float* Wk = (const float*)d_in[4];
    const float* bk = (const float*)d_in[5];
    const float* Wq = (const float*)d_in[6];
    const float* bq = (const float*)d_in[7];
    const float* Wv = (const float*)d_in[8];
    const float* bv = (const float*)d_in[9];
    const float* a_rel = (const float*)d_in[10];
    const float* m_rel = (const float*)d_in[11];
    const float* p_rel = (const float*)d_in[12];
    const float* Wo = (const float*)d_in[13];
    const float* bo = (const float*)d_in[14];
    const float* skip = (const float*)d_in[15];
    const int* ti_src = (const int*)d_in[16];
    const int* ti_dst = (const int*)d_in[17];
    const int* im_src = (const int*)d_in[18];
    const int* im_dst = (const int*)d_in[19];
    const int* ub_src = (const int*)d_in[20];
    const int* ub_dst = (const int*)d_in[21];
    const int* bu_src = (const int*)d_in[22];
    const int* bu_dst = (const int*)d_in[23];

    int nUser = in_sizes[0] / HID;
    int nItem = in_sizes[1] / HID;
    int nTaste = in_sizes[2] / HID;
    int nImage = in_sizes[3] / HID;
    int eTI = in_sizes[16], eIM = in_sizes[18], eUB = in_sizes[20], eBU = in_sizes[22];

    float* S = nullptr;
    cudaGetSymbolAddress((void**)&S, g_scratch);
    uint32_t* Wfrag = (uint32_t*)(S + OFF_WFRAG);
    float* Bias = S + OFF_BIAS;
    int* I = (int*)(S + OFF_CSRBASE);

    cudaFuncSetAttribute(mma_gemm_batch,
                         cudaFuncAttributeMaxDynamicSharedMemorySize, GEMM_SMEM);
    cudaFuncSetAttribute(mma_gemm_out,
                         cudaFuncAttributeMaxDynamicSharedMemorySize, GEMM_SMEM);

    // 1) prep weights into fragment layout (+ bias fold)
    prep_kernel<<<(98304 + 1536 + 255) / 256, 256>>>(
        Wk, bk, Wq, bq, Wv, bv, a_rel, m_rel, Wo, bo, Wfrag, Bias);

    // 2) zero CSR counters
    zero_int4<<<(17500 + 255) / 256, 256>>>((int4*)(I + ICNT_I), 17500);

    // 3) ALL projection GEMMs in one launch (KR/VR interleaved per node)
    GemmBatch GB;
    const float* xs[10] = {x_user, x_item, x_user, x_user, x_item,
                           x_item, x_taste, x_taste, x_image, x_image};
    int mats[10]        = {8, 9, 2, 6, 3, 7, 0, 4, 1, 5};
    long long offs[10]  = {OFF_Q_USER, OFF_Q_ITEM,
                           OFF_KV_USER, OFF_KV_USER + 128,
                           OFF_KV_ITEM, OFF_KV_ITEM + 128,
                           OFF_KV_TASTE, OFF_KV_TASTE + 128,
                           OFF_KV_IMAGE, OFF_KV_IMAGE + 128};
    int strides[10] = {128, 128, 256, 256, 256, 256, 256, 256, 256, 256};
    int ns[10] = {nUser, nItem, nUser, nUser, nItem, nItem, nTaste, nTaste, nImage, nImage};
    int maxTiles = 0;
    for (int i = 0; i < 10; i++) {
        GB.X[i] = xs[i];
        GB.W[i] = Wfrag + (size_t)mats[i] * 16384;
        GB.B[i] = Bias + mats[i] * 128;
        GB.Y[i] = S + offs[i];
        GB.N[i] = ns[i];
        GB.YS[i] = strides[i];
        int t = (ns[i] + 127) / 128;
        if (t > maxTiles) maxTiles = t;
    }
    mma_gemm_batch<<<dim3(maxTiles, 10), 256, GEMM_SMEM>>>(GB);

    // 4) CSR build
    EdgeIO E;
    E.src[0] = ti_src; E.dst[0] = ti_dst;
    E.src[1] = im_src; E.dst[1] = im_dst;
    E.src[2] = ub_src; E.dst[2] = ub_dst;
    E.src[3] = bu_src; E.dst[3] = bu_dst;
    E.off[0] = 0;
    E.off[1] = eTI;
    E.off[2] = eTI + eIM;
    E.off[3] = eTI + eIM + eUB;
    E.off[4] = eTI + eIM + eUB + eBU;
    int eTotal = E.off[4];
    hist_kernel<<<(eTotal + 255) / 256, 256>>>(E, I + ICNT_I, I + ICNT_U);
    scan_kernel<<<2, 1024>>>(I + ICNT_I, I + ISTART_I, nItem,
                             I + ICNT_U, I + ISTART_U, nUser);
    scatter_kernel<<<(eTotal + 255) / 256, 256>>>(E, I + ISTART_I, I + ISTART_U,
                                                  I + ICNT_I, I + ICNT_U,
                                                  I + ICSR_I, I + ICSR_U);

    // 5) gather: softmax aggregate + GELU
    GatherIO G;
    G.Qi = S + OFF_Q_ITEM;
    G.Qu = S + OFF_Q_USER;
    G.KV[0] = S + OFF_KV_TASTE;
    G.KV[1] = S + OFF_KV_IMAGE;
    G.KV[2] = S + OFF_KV_USER;
    G.KV[3] = S + OFF_KV_ITEM;
    G.csrI = I + ICSR_I;   G.csrU = I + ICSR_U;
    G.startI = I + ISTART_I; G.startU = I + ISTART_U;
    G.gelI = S + OFF_GEL_ITEM; G.gelU = S + OFF_GEL_USER;
    G.prel = p_rel;
    G.nI = nItem; G.nU = nUser;
    int warps = nItem + nUser;
    gather_kernel<<<(warps + 7) / 8, 256>>>(G);

    // 6) output projections with sigmoid-gated residual
    float* out_i = (float*)d_out;
    float* out_u = (float*)d_out + (size_t)nItem * HID;
    mma_gemm_out<<<(nItem + 127) / 128, 256, GEMM_SMEM>>>(
        S + OFF_GEL_ITEM, Wfrag + 10ull * 16384, Bias + 10 * 128, out_i, nItem,
        x_item, skip);
    mma_gemm_out<<<(nUser + 127) / 128, 256, GEMM_SMEM>>>(
        S + OFF_GEL_USER, Wfrag + 11ull * 16384, Bias + 11 * 128, out_u, nUser,
        x_user, skip + 1);

    (void)n_in; (void)out_size;
}

// round 11
// speedup vs baseline: 1.7945x; 1.0103x over previous
#include <cuda_runtime.h>
#include <cuda_bf16.h>
#include <math.h>
#include <stdint.h>

// ---------------------------------------------------------------------------
// MultiModalFusionGAT — mma.sync bf16x3 GEMM + CSR-gather edge phase.
//  * hist folded into the GEMM batch launch (extra grid.y row)
//  * CSR-counter zeroing folded into prep
//  * both output GEMMs fused into one launch (grid.y = 2)
// ---------------------------------------------------------------------------

#define HID 128

// scratch layout (floats)
#define OFF_Q_USER   0ll
#define OFF_Q_ITEM   2560000ll
#define OFF_KV_USER  8960000ll    // 20000 * 256 (kr | vr interleaved)
#define OFF_KV_ITEM  14080000ll   // 50000 * 256
#define OFF_KV_TASTE 26880000ll   // 50000 * 256
#define OFF_KV_IMAGE 39680000ll   // 50000 * 256
#define OFF_CSRBASE  52480000ll   // int region
#define OFF_GEL_ITEM 62000000ll
#define OFF_GEL_USER 68400000ll
#define OFF_WFRAG    70960000ll   // 12 mats x 16384 u32 (hi 8192 + lo 8192)
#define OFF_BIAS     71156608ll   // 12 x 128 floats
#define SCRATCH_TOTAL 71158144ll

// int offsets inside the CSR region (units: int32)
#define ICSR_I   0          // 600000 entries (item edges, packed src|seg<<16)
#define ICSR_U   600000     // 500000 entries (user edges, src)
#define ISTART_I 1100000    // 50001
#define ISTART_U 1150004    // 20001
#define ICNT_I   1170008    // 50000
#define ICNT_U   1220008    // 20000  (cnt arrays contiguous: 70000 total)

__device__ float g_scratch[SCRATCH_TOTAL];

struct EdgeIO {
    const int* src[4];
    const int* dst[4];
    int off[5];
};

struct GemmBatch {
    const float* X[10];
    const uint32_t* W[10];
    const float* B[10];
    float* Y[10];
    int N[10];
    int YS[10];   // output row stride (floats)
    EdgeIO E;     // for the fused hist row (blockIdx.y == 10)
    int* cntI;
    int* cntU;
};

struct OutBatch {
    const float* X[2];
    const uint32_t* W[2];
    const float* B[2];
    float* Y[2];
    const float* Res[2];
    const float* Skip;    // Skip[m]
    int N[2];
};

struct GatherIO {
    const float* Qi; const float* Qu;
    const float* KV[4];           // interleaved kr|vr, 256 floats/node
    const int* csrI; const int* csrU;
    const int* startI; const int* startU;
    float* gelI; float* gelU;
    const float* prel;
    int nI, nU;
};

// ---------------------------------------------------------------------------
__device__ __forceinline__ float foldW(int m, int k, int n,
        const float* __restrict__ Wk, const float* __restrict__ Wv,
        const float* __restrict__ Wq, const float* __restrict__ Wo,
        const float* __restrict__ a_rel, const float* __restrict__ m_rel) {
    if (m < 8) {
        int r = m & 3;
        int h = n >> 4, e = n & 15;
        int tsrc = (r == 0) ? 2 : (r == 1) ? 3 : (r == 2) ? 0 : 1;
        const float* Wsrc = (m < 4) ? Wk : Wv;
        const float* rel  = (m < 4) ? a_rel : m_rel;
        const float* wrow = Wsrc + tsrc * 16384 + k * 128 + h * 16;
        const float* arow = rel + r * 2048 + h * 256;
        float s = 0.f;
        #pragma unroll
        for (int d = 0; d < 16; d++) s += wrow[d] * arow[d * 16 + e];
        return s;
    } else if (m < 10) {
        return Wq[(m - 8) * 16384 + k * 128 + n];
    }
    return Wo[(m - 10) * 16384 + k * 128 + n];
}

__device__ __forceinline__ uint32_t packbf2(float a, float b) {
    __nv_bfloat16 ha = __float2bfloat16(a), hb = __float2bfloat16(b);
    return (uint32_t)__bfloat16_as_ushort(ha)
         | ((uint32_t)__bfloat16_as_ushort(hb) << 16);
}

// prep: weights -> fragment layout, bias fold, CSR counter zeroing (fused)
#define PREP_W   98304
#define PREP_B   (PREP_W + 1536)
#define PREP_Z   (PREP_B + 70000)
__global__ void prep_kernel(const float* __restrict__ Wk, const float* __restrict__ bk,
                            const float* __restrict__ Wq, const float* __restrict__ bq,
                            const float* __restrict__ Wv, const float* __restrict__ bv,
                            const float* __restrict__ a_rel, const float* __restrict__ m_rel,
                            const float* __restrict__ Wo, const float* __restrict__ bo,
                            uint32_t* __restrict__ Wfrag, float* __restrict__ Bias,
                            int* __restrict__ cnt) {
    int idx = blockIdx.x * blockDim.x + threadIdx.x;
    if (idx < PREP_W) {
        int m = idx >> 13;
        int rest = idx & 8191;
        int kc = rest >> 10;
        int rest2 = rest & 1023;
        int nt = rest2 >> 6;
        int e  = rest2 & 63;
        int lane = e >> 1, r = e & 1;
        int n  = nt * 8 + (lane >> 2);
        int k0 = kc * 16 + (lane & 3) * 2 + r * 8;
        float v0 = foldW(m, k0,     n, Wk, Wv, Wq, Wo, a_rel, m_rel);
        float v1 = foldW(m, k0 + 1, n, Wk, Wv, Wq, Wo, a_rel, m_rel);
        __nv_bfloat16 h0 = __float2bfloat16(v0), h1 = __float2bfloat16(v1);
        float l0 = v0 - __bfloat162float(h0), l1 = v1 - __bfloat162float(h1);
        uint32_t hi = (uint32_t)__bfloat16_as_ushort(h0)
                    | ((uint32_t)__bfloat16_as_ushort(h1) << 16);
        uint32_t lo = packbf2(l0, l1);
        size_t base = (size_t)m * 16384 + ((kc * 16 + nt) * 64 + e);
        Wfrag[base] = hi;
        Wfrag[base + 8192] = lo;
    } else if (idx < PREP_B) {
        int j = idx - PREP_W;
        int m = j >> 7, n = j & 127;
        float bval;
        if (m < 8) {
            int r = m & 3;
            int h = n >> 4, e2 = n & 15;
            int tsrc = (r == 0) ? 2 : (r == 1) ? 3 : (r == 2) ? 0 : 1;
            const float* bsrc = (m < 4) ? bk : bv;
            const float* rel  = (m < 4) ? a_rel : m_rel;
            const float* brow = bsrc + tsrc * 128 + h * 16;
            const float* arow = rel + r * 2048 + h * 256;
            float sb = 0.f;
            #pragma unroll
            for (int d = 0; d < 16; d++) sb += brow[d] * arow[d * 16 + e2];
            bval = sb;
        } else if (m < 10) {
            bval = bq[(m - 8) * 128 + n];
        } else {
            bval = bo[(m - 10) * 128 + n];
        }
        Bias[m * 128 + n] = bval;
    } else if (idx < PREP_Z) {
        cnt[idx - PREP_B] = 0;   // cntI | cntU contiguous (70000 ints)
    }
}

// ---------------------------------------------------------------------------
__device__ __forceinline__ void mma16816(float c[4], const uint32_t a[4],
                                         uint32_t b0, uint32_t b1) {
    asm volatile(
        "mma.sync.aligned.m16n8k16.row.col.f32.bf16.bf16.f32 "
        "{%0,%1,%2,%3}, {%4,%5,%6,%7}, {%8,%9}, {%0,%1,%2,%3};"
        : "+f"(c[0]), "+f"(c[1]), "+f"(c[2]), "+f"(c[3])
        : "r"(a[0]), "r"(a[1]), "r"(a[2]), "r"(a[3]), "r"(b0), "r"(b1));
}

__device__ __forceinline__ void split4(const float2& a, const float2& b,
                                       uint32_t& h01, uint32_t& l01,
                                       uint32_t& h23, uint32_t& l23) {
    __nv_bfloat16 ha = __float2bfloat16(a.x), hb = __float2bfloat16(a.y);
    __nv_bfloat16 hc = __float2bfloat16(b.x), hd = __float2bfloat16(b.y);
    h01 = (uint32_t)__bfloat16_as_ushort(ha) | ((uint32_t)__bfloat16_as_ushort(hb) << 16);
    h23 = (uint32_t)__bfloat16_as_ushort(hc) | ((uint32_t)__bfloat16_as_ushort(hd) << 16);
    l01 = packbf2(a.x - __bfloat162float(ha), a.y - __bfloat162float(hb));
    l23 = packbf2(b.x - __bfloat162float(hc), b.y - __bfloat162float(hd));
}

// Core 128x128 tile GEMM (bf16x3), pipelined kc loop.
__device__ __forceinline__ void gemm_tile(
        const float* __restrict__ X, const uint32_t* __restrict__ sW,
        const float* __restrict__ Bias, float* __restrict__ Y, int N, int tile0,
        int ystride, int mode, const float* __restrict__ Res, float g, float omg) {
    int tid = threadIdx.x;
    int warp = tid >> 5, lane = tid & 31;
    int rlo = tile0 + warp * 16 + (lane >> 2);
    int rhi = rlo + 8;
    bool oklo = rlo < N, okhi = rhi < N;
    const float* xlo = X + (size_t)rlo * 128;
    const float* xhi = X + (size_t)rhi * 128;
    int kb = (lane & 3) * 2;

    float C[16][4];
    #pragma unroll
    for (int nt = 0; nt < 16; nt++)
        #pragma unroll
        for (int j = 0; j < 4; j++) C[nt][j] = 0.f;

    float2 z2 = make_float2(0.f, 0.f);
    float2 p00 = oklo ? *(const float2*)(xlo + kb)     : z2;
    float2 p01 = oklo ? *(const float2*)(xlo + kb + 8) : z2;
    float2 p10 = okhi ? *(const float2*)(xhi + kb)     : z2;
    float2 p11 = okhi ? *(const float2*)(xhi + kb + 8) : z2;

    #pragma unroll 1
    for (int kc = 0; kc < 8; kc++) {
        float2 c00 = p00, c01 = p01, c10 = p10, c11 = p11;
        if (kc < 7) {
            int o = (kc + 1) * 16 + kb;
            p00 = oklo ? *(const float2*)(xlo + o)     : z2;
            p01 = oklo ? *(const float2*)(xlo + o + 8) : z2;
            p10 = okhi ? *(const float2*)(xhi + o)     : z2;
            p11 = okhi ? *(const float2*)(xhi + o + 8) : z2;
        }
        uint32_t ahi[4], alo[4];
        split4(c00, c10, ahi[0], alo[0], ahi[1], alo[1]);
        split4(c01, c11, ahi[2], alo[2], ahi[3], alo[3]);
        #pragma unroll
        for (int nt = 0; nt < 16; nt++) {
            uint32_t off = (uint32_t)((kc * 16 + nt) * 64 + lane * 2);
            uint2 bh = *(const uint2*)&sW[off];
            uint2 bl = *(const uint2*)&sW[off + 8192];
            mma16816(C[nt], ahi, bh.x, bh.y);
            mma16816(C[nt], alo, bh.x, bh.y);
            mma16816(C[nt], ahi, bl.x, bl.y);
        }
    }

    #pragma unroll
    for (int nt = 0; nt < 16; nt++) {
        int col = nt * 8 + kb;
        float2 b = *(const float2*)(Bias + col);
        if (oklo) {
            float2 o = make_float2(C[nt][0] + b.x, C[nt][1] + b.y);
            if (mode == 1) {
                float2 rv = *(const float2*)(Res + (size_t)rlo * 128 + col);
                o.x = g * o.x + omg * rv.x;
                o.y = g * o.y + omg * rv.y;
            }
            *(float2*)(Y + (size_t)rlo * ystride + col) = o;
        }
        if (okhi) {
            float2 o = make_float2(C[nt][2] + b.x, C[nt][3] + b.y);
            if (mode == 1) {
                float2 rv = *(const float2*)(Res + (size_t)rhi * 128 + col);
                o.x = g * o.x + omg * rv.x;
                o.y = g * o.y + omg * rv.y;
            }
            *(float2*)(Y + (size_t)rhi * ystride + col) = o;
        }
    }
}

#define GEMM_SMEM 65536

// batched projections + fused hist (blockIdx.y == 10)
__global__ void __launch_bounds__(256) mma_gemm_batch(GemmBatch P) {
    if (blockIdx.y == 10) {
        // grid-stride histogram over all edges (rides under the GEMM waves)
        int total = P.E.off[4];
        int stride = gridDim.x * 256;
        for (int g = blockIdx.x * 256 + threadIdx.x; g < total; g += stride) {
            int seg = (g >= P.E.off[1]) + (g >= P.E.off[2]) + (g >= P.E.off[3]);
            int e = g - P.E.off[seg];
            int d = P.E.dst[seg][e];
            atomicAdd((seg < 3) ? (P.cntI + d) : (P.cntU + d), 1);
        }
        return;
    }
    int m = blockIdx.y;
    int N = P.N[m];
    int tile0 = blockIdx.x * 128;
    if (tile0 >= N) return;
    extern __shared__ uint32_t sW[];
    {
        const uint4* src = (const uint4*)P.W[m];
        uint4* dst = (uint4*)sW;
        int tid = threadIdx.x;
        #pragma unroll
        for (int i = 0; i < 16; i++) dst[tid + i * 256] = src[tid + i * 256];
    }
    __syncthreads();
    gemm_tile(P.X[m], sW, P.B[m], P.Y[m], N, tile0, P.YS[m], 0, nullptr, 1.f, 0.f);
}

// fused output GEMMs (grid.y = 2) with sigmoid-gated residual
__global__ void __launch_bounds__(256) mma_gemm_out(OutBatch P) {
    int m = blockIdx.y;
    int N = P.N[m];
    int tile0 = blockIdx.x * 128;
    if (tile0 >= N) return;
    extern __shared__ uint32_t sW[];
    {
        const uint4* src = (const uint4*)P.W[m];
        uint4* dst = (uint4*)sW;
        int tid = threadIdx.x;
        #pragma unroll
        for (int i = 0; i < 16; i++) dst[tid + i * 256] = src[tid + i * 256];
    }
    __syncthreads();
    float g = 1.f / (1.f + expf(-P.Skip[m]));
    gemm_tile(P.X[m], sW, P.B[m], P.Y[m], N, tile0, 128, 1, P.Res[m], g, 1.f - g);
}

// ---------------------------------------------------------------------------
__global__ void scan_kernel(int* __restrict__ cntI, int* __restrict__ startI, int nI,
                            int* __restrict__ cntU, int* __restrict__ startU, int nU) {
    int* cnt   = blockIdx.x ? cntU : cntI;
    int* start = blockIdx.x ? startU : startI;
    int n      = blockIdx.x ? nU : nI;
    __shared__ int wsum[32];
    __shared__ int s_carry;
    int tid = threadIdx.x, lane = tid & 31, wid = tid >> 5;
    if (tid == 0) s_carry = 0;
    __syncthreads();
    for (int base = 0; base < n; base += 1024) {
        int i = base + tid;
        int v = (i < n) ? cnt[i] : 0;
        if (i < n) cnt[i] = 0;
        int incl = v;
        #pragma unroll
        for (int o = 1; o < 32; o <<= 1) {
            int t = __shfl_up_sync(0xFFFFFFFFu, incl, o);
            if (lane >= o) incl += t;
        }
        if (lane == 31) wsum[wid] = incl;
        __syncthreads();
        if (wid == 0) {
            int w = wsum[lane];
            int wi = w;
            #pragma unroll
            for (int o = 1; o < 32; o <<= 1) {
                int t = __shfl_up_sync(0xFFFFFFFFu, wi, o);
                if (lane >= o) wi += t;
            }
            wsum[lane] = wi - w;
        }
        __syncthreads();
        int excl = incl - v + wsum[wid] + s_carry;
        if (i < n) start[i] = excl;
        __syncthreads();
        if (tid == 1023) s_carry = excl + v;
        __syncthreads();
    }
    if (tid == 0) start[n] = s_carry;
}

__global__ void scatter_kernel(EdgeIO E,
                               const int* __restrict__ startI, const int* __restrict__ startU,
                               int* __restrict__ cntI, int* __restrict__ cntU,
                               int* __restrict__ csrI, int* __restrict__ csrU) {
    int g = blockIdx.x * 256 + threadIdx.x;
    if (g >= E.off[4]) return;
    int seg = (g >= E.off[1]) + (g >= E.off[2]) + (g >= E.off[3]);
    int e = g - E.off[seg];
    int d = E.dst[seg][e];
    int s = E.src[seg][e];
    if (seg < 3) {
        int pos = startI[d] + atomicAdd(cntI + d, 1);
        csrI[pos] = s | (seg << 16);
    } else {
        int pos = startU[d] + atomicAdd(cntU + d, 1);
        csrU[pos] = s;
    }
}

// warp-per-dst gather, unrolled x2: softmax aggregate + inline GELU
__global__ void __launch_bounds__(256) gather_kernel(GatherIO P) {
    int w = blockIdx.x * 8 + (threadIdx.x >> 5);
    int lane = threadIdx.x & 31;
    int h = lane >> 2;
    bool item = w < P.nI;
    int d = item ? w : w - P.nI;
    if (!item && d >= P.nU) return;

    const float* q = (item ? P.Qi : P.Qu) + (size_t)d * 128;
    float4 qv = *(const float4*)(q + lane * 4);
    const int* csr = item ? P.csrI : P.csrU;
    int js = item ? P.startI[d] : P.startU[d];
    int je = item ? P.startI[d + 1] : P.startU[d + 1];
    float p0, p1, p2;
    if (item) { p0 = P.prel[h]; p1 = P.prel[8 + h]; p2 = P.prel[16 + h]; }
    else      { p0 = p1 = p2 = P.prel[24 + h]; }

    float4 acc = make_float4(0.f, 0.f, 0.f, 0.f);
    float den = 0.f;
    int j = js;
    for (; j + 1 < je; j += 2) {
        int e0 = csr[j], e1 = csr[j + 1];
        int s0 = e0 & 0xFFFF, s1 = e1 & 0xFFFF;
        int g0 = item ? (e0 >> 16) : 3, g1 = item ? (e1 >> 16) : 3;
        const float* kv0b = P.KV[g0] + (size_t)s0 * 256;
        const float* kv1b = P.KV[g1] + (size_t)s1 * 256;
        float4 k0 = *(const float4*)(kv0b + lane * 4);
        float4 v0 = *(const float4*)(kv0b + 128 + lane * 4);
        float4 k1 = *(const float4*)(kv1b + lane * 4);
        float4 v1 = *(const float4*)(kv1b + 128 + lane * 4);
        float pa = qv.x * k0.x + qv.y * k0.y + qv.z * k0.z + qv.w * k0.w;
        float pb = qv.x * k1.x + qv.y * k1.y + qv.z * k1.z + qv.w * k1.w;
        pa += __shfl_xor_sync(0xFFFFFFFFu, pa, 1);
        pb += __shfl_xor_sync(0xFFFFFFFFu, pb, 1);
        pa += __shfl_xor_sync(0xFFFFFFFFu, pa, 2);
        pb += __shfl_xor_sync(0xFFFFFFFFu, pb, 2);
        float pr0 = item ? ((g0 == 0) ? p0 : ((g0 == 1) ? p1 : p2)) : p0;
        float pr1 = item ? ((g1 == 0) ? p0 : ((g1 == 1) ? p1 : p2)) : p0;
        float ex0 = __expf(pa * pr0 * 0.25f);
        float ex1 = __expf(pb * pr1 * 0.25f);
        den += ex0 + ex1;
        acc.x += ex0 * v0.x + ex1 * v1.x;
        acc.y += ex0 * v0.y + ex1 * v1.y;
        acc.z += ex0 * v0.z + ex1 * v1.z;
        acc.w += ex0 * v0.w + ex1 * v1.w;
    }
    if (j < je) {
        int e0 = csr[j];
        int s0 = e0 & 0xFFFF;
        int g0 = item ? (e0 >> 16) : 3;
        const float* kv0b = P.KV[g0] + (size_t)s0 * 256;
        float4 k0 = *(const float4*)(kv0b + lane * 4);
        float4 v0 = *(const float4*)(kv0b + 128 + lane * 4);
        float pa = qv.x * k0.x + qv.y * k0.y + qv.z * k0.z + qv.w * k0.w;
        pa += __shfl_xor_sync(0xFFFFFFFFu, pa, 1);
        pa += __shfl_xor_sync(0xFFFFFFFFu, pa, 2);
        float pr0 = item ? ((g0 == 0) ? p0 : ((g0 == 1) ? p1 : p2)) : p0;
        float ex0 = __expf(pa * pr0 * 0.25f);
        den += ex0;
        acc.x += ex0 * v0.x; acc.y += ex0 * v0.y;
        acc.z += ex0 * v0.z; acc.w += ex0 * v0.w;
    }
    float inv = 1.f / (den + 1e-16f);
    const float RS2 = 0.70710678118654752f;
    float4 o;
    float v;
    v = acc.x * inv; o.x = 0.5f * v * (1.f + erff(v * RS2));
    v = acc.y * inv; o.y = 0.5f * v * (1.f + erff(v * RS2));
    v = acc.z * inv; o.z = 0.5f * v * (1.f + erff(v * RS2));
    v = acc.w * inv; o.w = 0.5f * v * (1.f + erff(v * RS2));
    float* out = (item ? P.gelI : P.gelU) + (size_t)d * 128 + lane * 4;
    *(float4*)out = o;
}

// ---------------------------------------------------------------------------
extern "C" void kernel_launch(void* const* d_in, const int* in_sizes, int n_in,
                              void* d_out, int out_size) {
    const float* x_user = (const float*)d_in[0];
    const float* x_item = (const float*)d_in[1];
    const float* x_taste = (const float*)d_in[2];
    const float* x_image = (const float*)d_in[3];
    const float* Wk = (const float*)d_in[4];
    const float* bk = (const float*)d_in[5];
    const float* Wq = (const float*)d_in[6];
    const float* bq = (const float*)d_in[7];
    const float* Wv = (const float*)d_in[8];
    const float* bv = (const float*)d_in[9];
    const float* a_rel = (const float*)d_in[10];
    const float* m_rel = (const float*)d_in[11];
    const float* p_rel = (const float*)d_in[12];
    const float* Wo = (const float*)d_in[13];
    const float* bo = (const float*)d_in[14];
    const float* skip = (const float*)d_in[15];
    const int* ti_src = (const int*)d_in[16];
    const int* ti_dst = (const int*)d_in[17];
    const int* im_src = (const int*)d_in[18];
    const int* im_dst = (const int*)d_in[19];
    const int* ub_src = (const int*)d_in[20];
    const int* ub_dst = (const int*)d_in[21];
    const int* bu_src = (const int*)d_in[22];
    const int* bu_dst = (const int*)d_in[23];

    int nUser = in_sizes[0] / HID;
    int nItem = in_sizes[1] / HID;
    int nTaste = in_sizes[2] / HID;
    int nImage = in_sizes[3] / HID;
    int eTI = in_sizes[16], eIM = in_sizes[18], eUB = in_sizes[20], eBU = in_sizes[22];

    float* S = nullptr;
    cudaGetSymbolAddress((void**)&S, g_scratch);
    uint32_t* Wfrag = (uint32_t*)(S + OFF_WFRAG);
    float* Bias = S + OFF_BIAS;
    int* I = (int*)(S + OFF_CSRBASE);

    cudaFuncSetAttribute(mma_gemm_batch,
                         cudaFuncAttributeMaxDynamicSharedMemorySize, GEMM_SMEM);
    cudaFuncSetAttribute(mma_gemm_out,
                         cudaFuncAttributeMaxDynamicSharedMemorySize, GEMM_SMEM);

    // edge tables
    EdgeIO E;
    E.src[0] = ti_src; E.dst[0] = ti_dst;
    E.src[1] = im_src; E.dst[1] = im_dst;
    E.src[2] = ub_src; E.dst[2] = ub_dst;
    E.src[3] = bu_src; E.dst[3] = bu_dst;
    E.off[0] = 0;
    E.off[1] = eTI;
    E.off[2] = eTI + eIM;
    E.off[3] = eTI + eIM + eUB;
    E.off[4] = eTI + eIM + eUB + eBU;
    int eTotal = E.off[4];

    // 1) prep weights + bias + zero CSR counters (one launch)
    prep_kernel<<<(PREP_Z + 255) / 256, 256>>>(
        Wk, bk, Wq, bq, Wv, bv, a_rel, m_rel, Wo, bo, Wfrag, Bias, I + ICNT_I);

    // 2) ALL projection GEMMs + hist in one launch
    GemmBatch GB;
    const float* xs[10] = {x_user, x_item, x_user, x_user, x_item,
                           x_item, x_taste, x_taste, x_image, x_image};
    int mats[10]        = {8, 9, 2, 6, 3, 7, 0, 4, 1, 5};
    long long offs[10]  = {OFF_Q_USER, OFF_Q_ITEM,
                           OFF_KV_USER, OFF_KV_USER + 128,
                           OFF_KV_ITEM, OFF_KV_ITEM + 128,
                           OFF_KV_TASTE, OFF_KV_TASTE + 128,
                           OFF_KV_IMAGE, OFF_KV_IMAGE + 128};
    int strides[10] = {128, 128, 256, 256, 256, 256, 256, 256, 256, 256};
    int ns[10] = {nUser, nItem, nUser, nUser, nItem, nItem, nTaste, nTaste, nImage, nImage};
    int maxTiles = 0;
    for (int i = 0; i < 10; i++) {
        GB.X[i] = xs[i];
        GB.W[i] = Wfrag + (size_t)mats[i] * 16384;
        GB.B[i] = Bias + mats[i] * 128;
        GB.Y[i] = S + offs[i];
        GB.N[i] = ns[i];
        GB.YS[i] = strides[i];
        int t = (ns[i] + 127) / 128;
        if (t > maxTiles) maxTiles = t;
    }
    GB.E = E;
    GB.cntI = I + ICNT_I;
    GB.cntU = I + ICNT_U;
    mma_gemm_batch<<<dim3(maxTiles, 11), 256, GEMM_SMEM>>>(GB);

    // 3) CSR: scan + scatter
    scan_kernel<<<2, 1024>>>(I + ICNT_I, I + ISTART_I, nItem,
                             I + ICNT_U, I + ISTART_U, nUser);
    scatter_kernel<<<(eTotal + 255) / 256, 256>>>(E, I + ISTART_I, I + ISTART_U,
                                                  I + ICNT_I, I + ICNT_U,
                                                  I + ICSR_I, I + ICSR_U);

    // 4) gather: softmax aggregate + GELU
    GatherIO G;
    G.Qi = S + OFF_Q_ITEM;
    G.Qu = S + OFF_Q_USER;
    G.KV[0] = S + OFF_KV_TASTE;
    G.KV[1] = S + OFF_KV_IMAGE;
    G.KV[2] = S + OFF_KV_USER;
    G.KV[3] = S + OFF_KV_ITEM;
    G.csrI = I + ICSR_I;   G.csrU = I + ICSR_U;
    G.startI = I + ISTART_I; G.startU = I + ISTART_U;
    G.gelI = S + OFF_GEL_ITEM; G.gelU = S + OFF_GEL_USER;
    G.prel = p_rel;
    G.nI = nItem; G.nU = nUser;
    int warps = nItem + nUser;
    gather_kernel<<<(warps + 7) / 8, 256>>>(G);

    // 5) fused output projections with sigmoid-gated residual
    float* out_i = (float*)d_out;
    float* out_u = (float*)d_out + (size_t)nItem * HID;
    OutBatch OB;
    OB.X[0] = S + OFF_GEL_ITEM; OB.X[1] = S + OFF_GEL_USER;
    OB.W[0] = Wfrag + 10ull * 16384; OB.W[1] = Wfrag + 11ull * 16384;
    OB.B[0] = Bias + 10 * 128; OB.B[1] = Bias + 11 * 128;
    OB.Y[0] = out_i; OB.Y[1] = out_u;
    OB.Res[0] = x_item; OB.Res[1] = x_user;
    OB.Skip = skip;
    OB.N[0] = nItem; OB.N[1] = nUser;
    int outTiles = ((nItem > nUser ? nItem : nUser) + 127) / 128;
    mma_gemm_out<<<dim3(outTiles, 2), 256, GEMM_SMEM>>>(OB);

    (void)n_in; (void)out_size;
}

// round 12
// speedup vs baseline: 1.8792x; 1.0472x over previous
#include <cuda_runtime.h>
#include <cuda_bf16.h>
#include <math.h>
#include <stdint.h>

// ---------------------------------------------------------------------------
// MultiModalFusionGAT — mma.sync bf16x3 GEMM + CSR-gather edge phase.
//  * projection GEMMs: PERSISTENT CTAs over flattened (matrix,tile) space —
//    weights loaded once per CTA-chunk instead of once per tile
//  * hist fused (grid.y==1), CSR-counter zero fused into prep
//  * output GEMMs fused into one launch (grid.y = 2)
// ---------------------------------------------------------------------------

#define HID 128

// scratch layout (floats)
#define OFF_Q_USER   0ll
#define OFF_Q_ITEM   2560000ll
#define OFF_KV_USER  8960000ll    // 20000 * 256 (kr | vr interleaved)
#define OFF_KV_ITEM  14080000ll   // 50000 * 256
#define OFF_KV_TASTE 26880000ll   // 50000 * 256
#define OFF_KV_IMAGE 39680000ll   // 50000 * 256
#define OFF_CSRBASE  52480000ll   // int region
#define OFF_GEL_ITEM 62000000ll
#define OFF_GEL_USER 68400000ll
#define OFF_WFRAG    70960000ll   // 12 mats x 16384 u32 (hi 8192 + lo 8192)
#define OFF_BIAS     71156608ll   // 12 x 128 floats
#define SCRATCH_TOTAL 71158144ll

// int offsets inside the CSR region (units: int32)
#define ICSR_I   0          // 600000 entries (item edges, packed src|seg<<16)
#define ICSR_U   600000     // 500000 entries (user edges, src)
#define ISTART_I 1100000    // 50001
#define ISTART_U 1150004    // 20001
#define ICNT_I   1170008    // 50000
#define ICNT_U   1220008    // 20000  (cnt arrays contiguous: 70000 total)

#define NCTA_GEMM 296       // persistent GEMM CTAs (2 per SM, one wave)

__device__ float g_scratch[SCRATCH_TOTAL];

struct EdgeIO {
    const int* src[4];
    const int* dst[4];
    int off[5];
};

struct GemmBatch {
    const float* X[10];
    const uint32_t* W[10];
    const float* B[10];
    float* Y[10];
    int N[10];
    int YS[10];        // output row stride (floats)
    int tileStart[11]; // prefix sums of per-matrix tile counts
    int chunk;         // tiles per persistent CTA
    EdgeIO E;          // for the fused hist slice (blockIdx.y == 1)
    int* cntI;
    int* cntU;
};

struct OutBatch {
    const float* X[2];
    const uint32_t* W[2];
    const float* B[2];
    float* Y[2];
    const float* Res[2];
    const float* Skip;
    int N[2];
};

struct GatherIO {
    const float* Qi; const float* Qu;
    const float* KV[4];           // interleaved kr|vr, 256 floats/node
    const int* csrI; const int* csrU;
    const int* startI; const int* startU;
    float* gelI; float* gelU;
    const float* prel;
    int nI, nU;
};

// ---------------------------------------------------------------------------
__device__ __forceinline__ float foldW(int m, int k, int n,
        const float* __restrict__ Wk, const float* __restrict__ Wv,
        const float* __restrict__ Wq, const float* __restrict__ Wo,
        const float* __restrict__ a_rel, const float* __restrict__ m_rel) {
    if (m < 8) {
        int r = m & 3;
        int h = n >> 4, e = n & 15;
        int tsrc = (r == 0) ? 2 : (r == 1) ? 3 : (r == 2) ? 0 : 1;
        const float* Wsrc = (m < 4) ? Wk : Wv;
        const float* rel  = (m < 4) ? a_rel : m_rel;
        const float* wrow = Wsrc + tsrc * 16384 + k * 128 + h * 16;
        const float* arow = rel + r * 2048 + h * 256;
        float s = 0.f;
        #pragma unroll
        for (int d = 0; d < 16; d++) s += wrow[d] * arow[d * 16 + e];
        return s;
    } else if (m < 10) {
        return Wq[(m - 8) * 16384 + k * 128 + n];
    }
    return Wo[(m - 10) * 16384 + k * 128 + n];
}

__device__ __forceinline__ uint32_t packbf2(float a, float b) {
    __nv_bfloat16 ha = __float2bfloat16(a), hb = __float2bfloat16(b);
    return (uint32_t)__bfloat16_as_ushort(ha)
         | ((uint32_t)__bfloat16_as_ushort(hb) << 16);
}

// prep: weights -> fragment layout, bias fold, CSR counter zeroing (fused)
#define PREP_W   98304
#define PREP_B   (PREP_W + 1536)
#define PREP_Z   (PREP_B + 70000)
__global__ void prep_kernel(const float* __restrict__ Wk, const float* __restrict__ bk,
                            const float* __restrict__ Wq, const float* __restrict__ bq,
                            const float* __restrict__ Wv, const float* __restrict__ bv,
                            const float* __restrict__ a_rel, const float* __restrict__ m_rel,
                            const float* __restrict__ Wo, const float* __restrict__ bo,
                            uint32_t* __restrict__ Wfrag, float* __restrict__ Bias,
                            int* __restrict__ cnt) {
    int idx = blockIdx.x * blockDim.x + threadIdx.x;
    if (idx < PREP_W) {
        int m = idx >> 13;
        int rest = idx & 8191;
        int kc = rest >> 10;
        int rest2 = rest & 1023;
        int nt = rest2 >> 6;
        int e  = rest2 & 63;
        int lane = e >> 1, r = e & 1;
        int n  = nt * 8 + (lane >> 2);
        int k0 = kc * 16 + (lane & 3) * 2 + r * 8;
        float v0 = foldW(m, k0,     n, Wk, Wv, Wq, Wo, a_rel, m_rel);
        float v1 = foldW(m, k0 + 1, n, Wk, Wv, Wq, Wo, a_rel, m_rel);
        __nv_bfloat16 h0 = __float2bfloat16(v0), h1 = __float2bfloat16(v1);
        float l0 = v0 - __bfloat162float(h0), l1 = v1 - __bfloat162float(h1);
        uint32_t hi = (uint32_t)__bfloat16_as_ushort(h0)
                    | ((uint32_t)__bfloat16_as_ushort(h1) << 16);
        uint32_t lo = packbf2(l0, l1);
        size_t base = (size_t)m * 16384 + ((kc * 16 + nt) * 64 + e);
        Wfrag[base] = hi;
        Wfrag[base + 8192] = lo;
    } else if (idx < PREP_B) {
        int j = idx - PREP_W;
        int m = j >> 7, n = j & 127;
        float bval;
        if (m < 8) {
            int r = m & 3;
            int h = n >> 4, e2 = n & 15;
            int tsrc = (r == 0) ? 2 : (r == 1) ? 3 : (r == 2) ? 0 : 1;
            const float* bsrc = (m < 4) ? bk : bv;
            const float* rel  = (m < 4) ? a_rel : m_rel;
            const float* brow = bsrc + tsrc * 128 + h * 16;
            const float* arow = rel + r * 2048 + h * 256;
            float sb = 0.f;
            #pragma unroll
            for (int d = 0; d < 16; d++) sb += brow[d] * arow[d * 16 + e2];
            bval = sb;
        } else if (m < 10) {
            bval = bq[(m - 8) * 128 + n];
        } else {
            bval = bo[(m - 10) * 128 + n];
        }
        Bias[m * 128 + n] = bval;
    } else if (idx < PREP_Z) {
        cnt[idx - PREP_B] = 0;   // cntI | cntU contiguous (70000 ints)
    }
}

// ---------------------------------------------------------------------------
__device__ __forceinline__ void mma16816(float c[4], const uint32_t a[4],
                                         uint32_t b0, uint32_t b1) {
    asm volatile(
        "mma.sync.aligned.m16n8k16.row.col.f32.bf16.bf16.f32 "
        "{%0,%1,%2,%3}, {%4,%5,%6,%7}, {%8,%9}, {%0,%1,%2,%3};"
        : "+f"(c[0]), "+f"(c[1]), "+f"(c[2]), "+f"(c[3])
        : "r"(a[0]), "r"(a[1]), "r"(a[2]), "r"(a[3]), "r"(b0), "r"(b1));
}

__device__ __forceinline__ void split4(const float2& a, const float2& b,
                                       uint32_t& h01, uint32_t& l01,
                                       uint32_t& h23, uint32_t& l23) {
    __nv_bfloat16 ha = __float2bfloat16(a.x), hb = __float2bfloat16(a.y);
    __nv_bfloat16 hc = __float2bfloat16(b.x), hd = __float2bfloat16(b.y);
    h01 = (uint32_t)__bfloat16_as_ushort(ha) | ((uint32_t)__bfloat16_as_ushort(hb) << 16);
    h23 = (uint32_t)__bfloat16_as_ushort(hc) | ((uint32_t)__bfloat16_as_ushort(hd) << 16);
    l01 = packbf2(a.x - __bfloat162float(ha), a.y - __bfloat162float(hb));
    l23 = packbf2(b.x - __bfloat162float(hc), b.y - __bfloat162float(hd));
}

// Core 128x128 tile GEMM (bf16x3), pipelined kc loop.
__device__ __forceinline__ void gemm_tile(
        const float* __restrict__ X, const uint32_t* __restrict__ sW,
        const float* __restrict__ Bias, float* __restrict__ Y, int N, int tile0,
        int ystride, int mode, const float* __restrict__ Res, float g, float omg) {
    int tid = threadIdx.x;
    int warp = tid >> 5, lane = tid & 31;
    int rlo = tile0 + warp * 16 + (lane >> 2);
    int rhi = rlo + 8;
    bool oklo = rlo < N, okhi = rhi < N;
    const float* xlo = X + (size_t)rlo * 128;
    const float* xhi = X + (size_t)rhi * 128;
    int kb = (lane & 3) * 2;

    float C[16][4];
    #pragma unroll
    for (int nt = 0; nt < 16; nt++)
        #pragma unroll
        for (int j = 0; j < 4; j++) C[nt][j] = 0.f;

    float2 z2 = make_float2(0.f, 0.f);
    float2 p00 = oklo ? *(const float2*)(xlo + kb)     : z2;
    float2 p01 = oklo ? *(const float2*)(xlo + kb + 8) : z2;
    float2 p10 = okhi ? *(const float2*)(xhi + kb)     : z2;
    float2 p11 = okhi ? *(const float2*)(xhi + kb + 8) : z2;

    #pragma unroll 1
    for (int kc = 0; kc < 8; kc++) {
        float2 c00 = p00, c01 = p01, c10 = p10, c11 = p11;
        if (kc < 7) {
            int o = (kc + 1) * 16 + kb;
            p00 = oklo ? *(const float2*)(xlo + o)     : z2;
            p01 = oklo ? *(const float2*)(xlo + o + 8) : z2;
            p10 = okhi ? *(const float2*)(xhi + o)     : z2;
            p11 = okhi ? *(const float2*)(xhi + o + 8) : z2;
        }
        uint32_t ahi[4], alo[4];
        split4(c00, c10, ahi[0], alo[0], ahi[1], alo[1]);
        split4(c01, c11, ahi[2], alo[2], ahi[3], alo[3]);
        #pragma unroll
        for (int nt = 0; nt < 16; nt++) {
            uint32_t off = (uint32_t)((kc * 16 + nt) * 64 + lane * 2);
            uint2 bh = *(const uint2*)&sW[off];
            uint2 bl = *(const uint2*)&sW[off + 8192];
            mma16816(C[nt], ahi, bh.x, bh.y);
            mma16816(C[nt], alo, bh.x, bh.y);
            mma16816(C[nt], ahi, bl.x, bl.y);
        }
    }

    #pragma unroll
    for (int nt = 0; nt < 16; nt++) {
        int col = nt * 8 + kb;
        float2 b = *(const float2*)(Bias + col);
        if (oklo) {
            float2 o = make_float2(C[nt][0] + b.x, C[nt][1] + b.y);
            if (mode == 1) {
                float2 rv = *(const float2*)(Res + (size_t)rlo * 128 + col);
                o.x = g * o.x + omg * rv.x;
                o.y = g * o.y + omg * rv.y;
            }
            *(float2*)(Y + (size_t)rlo * ystride + col) = o;
        }
        if (okhi) {
            float2 o = make_float2(C[nt][2] + b.x, C[nt][3] + b.y);
            if (mode == 1) {
                float2 rv = *(const float2*)(Res + (size_t)rhi * 128 + col);
                o.x = g * o.x + omg * rv.x;
                o.y = g * o.y + omg * rv.y;
            }
            *(float2*)(Y + (size_t)rhi * ystride + col) = o;
        }
    }
}

#define GEMM_SMEM 65536

// persistent batched projections (grid.y==0) + fused hist (grid.y==1)
__global__ void __launch_bounds__(256) mma_gemm_batch(GemmBatch P) {
    if (blockIdx.y == 1) {
        int total = P.E.off[4];
        int stride = gridDim.x * 256;
        for (int g = blockIdx.x * 256 + threadIdx.x; g < total; g += stride) {
            int seg = (g >= P.E.off[1]) + (g >= P.E.off[2]) + (g >= P.E.off[3]);
            int e = g - P.E.off[seg];
            int d = P.E.dst[seg][e];
            atomicAdd((seg < 3) ? (P.cntI + d) : (P.cntU + d), 1);
        }
        return;
    }
    extern __shared__ uint32_t sW[];
    int total = P.tileStart[10];
    int t0 = blockIdx.x * P.chunk;
    int t1 = t0 + P.chunk;
    if (t1 > total) t1 = total;
    int cur = -1;
    for (int t = t0; t < t1; t++) {
        if (cur < 0 || t >= P.tileStart[cur + 1]) {
            int m = (cur < 0) ? 0 : cur + 1;
            while (t >= P.tileStart[m + 1]) m++;
            __syncthreads();   // all warps done reading old weights
            const uint4* src = (const uint4*)P.W[m];
            uint4* dst = (uint4*)sW;
            int tid = threadIdx.x;
            #pragma unroll
            for (int i = 0; i < 16; i++) dst[tid + i * 256] = src[tid + i * 256];
            __syncthreads();
            cur = m;
        }
        gemm_tile(P.X[cur], sW, P.B[cur], P.Y[cur], P.N[cur],
                  (t - P.tileStart[cur]) * 128, P.YS[cur], 0, nullptr, 1.f, 0.f);
    }
}

// fused output GEMMs (grid.y = 2) with sigmoid-gated residual
__global__ void __launch_bounds__(256) mma_gemm_out(OutBatch P) {
    int m = blockIdx.y;
    int N = P.N[m];
    int tile0 = blockIdx.x * 128;
    if (tile0 >= N) return;
    extern __shared__ uint32_t sW[];
    {
        const uint4* src = (const uint4*)P.W[m];
        uint4* dst = (uint4*)sW;
        int tid = threadIdx.x;
        #pragma unroll
        for (int i = 0; i < 16; i++) dst[tid + i * 256] = src[tid + i * 256];
    }
    __syncthreads();
    float g = 1.f / (1.f + expf(-P.Skip[m]));
    gemm_tile(P.X[m], sW, P.B[m], P.Y[m], N, tile0, 128, 1, P.Res[m], g, 1.f - g);
}

// ---------------------------------------------------------------------------
__global__ void scan_kernel(int* __restrict__ cntI, int* __restrict__ startI, int nI,
                            int* __restrict__ cntU, int* __restrict__ startU, int nU) {
    int* cnt   = blockIdx.x ? cntU : cntI;
    int* start = blockIdx.x ? startU : startI;
    int n      = blockIdx.x ? nU : nI;
    __shared__ int wsum[32];
    __shared__ int s_carry;
    int tid = threadIdx.x, lane = tid & 31, wid = tid >> 5;
    if (tid == 0) s_carry = 0;
    __syncthreads();
    for (int base = 0; base < n; base += 1024) {
        int i = base + tid;
        int v = (i < n) ? cnt[i] : 0;
        if (i < n) cnt[i] = 0;
        int incl = v;
        #pragma unroll
        for (int o = 1; o < 32; o <<= 1) {
            int t = __shfl_up_sync(0xFFFFFFFFu, incl, o);
            if (lane >= o) incl += t;
        }
        if (lane == 31) wsum[wid] = incl;
        __syncthreads();
        if (wid == 0) {
            int w = wsum[lane];
            int wi = w;
            #pragma unroll
            for (int o = 1; o < 32; o <<= 1) {
                int t = __shfl_up_sync(0xFFFFFFFFu, wi, o);
                if (lane >= o) wi += t;
            }
            wsum[lane] = wi - w;
        }
        __syncthreads();
        int excl = incl - v + wsum[wid] + s_carry;
        if (i < n) start[i] = excl;
        __syncthreads();
        if (tid == 1023) s_carry = excl + v;
        __syncthreads();
    }
    if (tid == 0) start[n] = s_carry;
}

__global__ void scatter_kernel(EdgeIO E,
                               const int* __restrict__ startI, const int* __restrict__ startU,
                               int* __restrict__ cntI, int* __restrict__ cntU,
                               int* __restrict__ csrI, int* __restrict__ csrU) {
    int g = blockIdx.x * 256 + threadIdx.x;
    if (g >= E.off[4]) return;
    int seg = (g >= E.off[1]) + (g >= E.off[2]) + (g >= E.off[3]);
    int e = g - E.off[seg];
    int d = E.dst[seg][e];
    int s = E.src[seg][e];
    if (seg < 3) {
        int pos = startI[d] + atomicAdd(cntI + d, 1);
        csrI[pos] = s | (seg << 16);
    } else {
        int pos = startU[d] + atomicAdd(cntU + d, 1);
        csrU[pos] = s;
    }
}

// warp-per-dst gather, unrolled x2: softmax aggregate + inline GELU
__global__ void __launch_bounds__(256) gather_kernel(GatherIO P) {
    int w = blockIdx.x * 8 + (threadIdx.x >> 5);
    int lane = threadIdx.x & 31;
    int h = lane >> 2;
    bool item = w < P.nI;
    int d = item ? w : w - P.nI;
    if (!item && d >= P.nU) return;

    const float* q = (item ? P.Qi : P.Qu) + (size_t)d * 128;
    float4 qv = *(const float4*)(q + lane * 4);
    const int* csr = item ? P.csrI : P.csrU;
    int js = item ? P.startI[d] : P.startU[d];
    int je = item ? P.startI[d + 1] : P.startU[d + 1];
    float p0, p1, p2;
    if (item) { p0 = P.prel[h]; p1 = P.prel[8 + h]; p2 = P.prel[16 + h]; }
    else      { p0 = p1 = p2 = P.prel[24 + h]; }

    float4 acc = make_float4(0.f, 0.f, 0.f, 0.f);
    float den = 0.f;
    int j = js;
    for (; j + 1 < je; j += 2) {
        int e0 = csr[j], e1 = csr[j + 1];
        int s0 = e0 & 0xFFFF, s1 = e1 & 0xFFFF;
        int g0 = item ? (e0 >> 16) : 3, g1 = item ? (e1 >> 16) : 3;
        const float* kv0b = P.KV[g0] + (size_t)s0 * 256;
        const float* kv1b = P.KV[g1] + (size_t)s1 * 256;
        float4 k0 = *(const float4*)(kv0b + lane * 4);
        float4 v0 = *(const float4*)(kv0b + 128 + lane * 4);
        float4 k1 = *(const float4*)(kv1b + lane * 4);
        float4 v1 = *(const float4*)(kv1b + 128 + lane * 4);
        float pa = qv.x * k0.x + qv.y * k0.y + qv.z * k0.z + qv.w * k0.w;
        float pb = qv.x * k1.x + qv.y * k1.y + qv.z * k1.z + qv.w * k1.w;
        pa += __shfl_xor_sync(0xFFFFFFFFu, pa, 1);
        pb += __shfl_xor_sync(0xFFFFFFFFu, pb, 1);
        pa += __shfl_xor_sync(0xFFFFFFFFu, pa, 2);
        pb += __shfl_xor_sync(0xFFFFFFFFu, pb, 2);
        float pr0 = item ? ((g0 == 0) ? p0 : ((g0 == 1) ? p1 : p2)) : p0;
        float pr1 = item ? ((g1 == 0) ? p0 : ((g1 == 1) ? p1 : p2)) : p0;
        float ex0 = __expf(pa * pr0 * 0.25f);
        float ex1 = __expf(pb * pr1 * 0.25f);
        den += ex0 + ex1;
        acc.x += ex0 * v0.x + ex1 * v1.x;
        acc.y += ex0 * v0.y + ex1 * v1.y;
        acc.z += ex0 * v0.z + ex1 * v1.z;
        acc.w += ex0 * v0.w + ex1 * v1.w;
    }
    if (j < je) {
        int e0 = csr[j];
        int s0 = e0 & 0xFFFF;
        int g0 = item ? (e0 >> 16) : 3;
        const float* kv0b = P.KV[g0] + (size_t)s0 * 256;
        float4 k0 = *(const float4*)(kv0b + lane * 4);
        float4 v0 = *(const float4*)(kv0b + 128 + lane * 4);
        float pa = qv.x * k0.x + qv.y * k0.y + qv.z * k0.z + qv.w * k0.w;
        pa += __shfl_xor_sync(0xFFFFFFFFu, pa, 1);
        pa += __shfl_xor_sync(0xFFFFFFFFu, pa, 2);
        float pr0 = item ? ((g0 == 0) ? p0 : ((g0 == 1) ? p1 : p2)) : p0;
        float ex0 = __expf(pa * pr0 * 0.25f);
        den += ex0;
        acc.x += ex0 * v0.x; acc.y += ex0 * v0.y;
        acc.z += ex0 * v0.z; acc.w += ex0 * v0.w;
    }
    float inv = 1.f / (den + 1e-16f);
    const float RS2 = 0.70710678118654752f;
    float4 o;
    float v;
    v = acc.x * inv; o.x = 0.5f * v * (1.f + erff(v * RS2));
    v = acc.y * inv; o.y = 0.5f * v * (1.f + erff(v * RS2));
    v = acc.z * inv; o.z = 0.5f * v * (1.f + erff(v * RS2));
    v = acc.w * inv; o.w = 0.5f * v * (1.f + erff(v * RS2));
    float* out = (item ? P.gelI : P.gelU) + (size_t)d * 128 + lane * 4;
    *(float4*)out = o;
}

// ---------------------------------------------------------------------------
extern "C" void kernel_launch(void* const* d_in, const int* in_sizes, int n_in,
                              void* d_out, int out_size) {
    const float* x_user = (const float*)d_in[0];
    const float* x_item = (const float*)d_in[1];
    const float* x_taste = (const float*)d_in[2];
    const float* x_image = (const float*)d_in[3];
    const float* Wk = (const float*)d_in[4];
    const float* bk = (const float*)d_in[5];
    const float* Wq = (const float*)d_in[6];
    const float* bq = (const float*)d_in[7];
    const float* Wv = (const float*)d_in[8];
    const float* bv = (const float*)d_in[9];
    const float* a_rel = (const float*)d_in[10];
    const float* m_rel = (const float*)d_in[11];
    const float* p_rel = (const float*)d_in[12];
    const float* Wo = (const float*)d_in[13];
    const float* bo = (const float*)d_in[14];
    const float* skip = (const float*)d_in[15];
    const int* ti_src = (const int*)d_in[16];
    const int* ti_dst = (const int*)d_in[17];
    const int* im_src = (const int*)d_in[18];
    const int* im_dst = (const int*)d_in[19];
    const int* ub_src = (const int*)d_in[20];
    const int* ub_dst = (const int*)d_in[21];
    const int* bu_src = (const int*)d_in[22];
    const int* bu_dst = (const int*)d_in[23];

    int nUser = in_sizes[0] / HID;
    int nItem = in_sizes[1] / HID;
    int nTaste = in_sizes[2] / HID;
    int nImage = in_sizes[3] / HID;
    int eTI = in_sizes[16], eIM = in_sizes[18], eUB = in_sizes[20], eBU = in_sizes[22];

    float* S = nullptr;
    cudaGetSymbolAddress((void**)&S, g_scratch);
    uint32_t* Wfrag = (uint32_t*)(S + OFF_WFRAG);
    float* Bias = S + OFF_BIAS;
    int* I = (int*)(S + OFF_CSRBASE);

    cudaFuncSetAttribute(mma_gemm_batch,
                         cudaFuncAttributeMaxDynamicSharedMemorySize, GEMM_SMEM);
    cudaFuncSetAttribute(mma_gemm_out,
                         cudaFuncAttributeMaxDynamicSharedMemorySize, GEMM_SMEM);

    // edge tables
    EdgeIO E;
    E.src[0] = ti_src; E.dst[0] = ti_dst;
    E.src[1] = im_src; E.dst[1] = im_dst;
    E.src[2] = ub_src; E.dst[2] = ub_dst;
    E.src[3] = bu_src; E.dst[3] = bu_dst;
    E.off[0] = 0;
    E.off[1] = eTI;
    E.off[2] = eTI + eIM;
    E.off[3] = eTI + eIM + eUB;
    E.off[4] = eTI + eIM + eUB + eBU;
    int eTotal = E.off[4];

    // 1) prep weights + bias + zero CSR counters (one launch)
    prep_kernel<<<(PREP_Z + 255) / 256, 256>>>(
        Wk, bk, Wq, bq, Wv, bv, a_rel, m_rel, Wo, bo, Wfrag, Bias, I + ICNT_I);

    // 2) persistent projection GEMMs + hist, one launch
    GemmBatch GB;
    const float* xs[10] = {x_user, x_item, x_user, x_user, x_item,
                           x_item, x_taste, x_taste, x_image, x_image};
    int mats[10]        = {8, 9, 2, 6, 3, 7, 0, 4, 1, 5};
    long long offs[10]  = {OFF_Q_USER, OFF_Q_ITEM,
                           OFF_KV_USER, OFF_KV_USER + 128,
                           OFF_KV_ITEM, OFF_KV_ITEM + 128,
                           OFF_KV_TASTE, OFF_KV_TASTE + 128,
                           OFF_KV_IMAGE, OFF_KV_IMAGE + 128};
    int strides[10] = {128, 128, 256, 256, 256, 256, 256, 256, 256, 256};
    int ns[10] = {nUser, nItem, nUser, nUser, nItem, nItem, nTaste, nTaste, nImage, nImage};
    int tsum = 0;
    for (int i = 0; i < 10; i++) {
        GB.X[i] = xs[i];
        GB.W[i] = Wfrag + (size_t)mats[i] * 16384;
        GB.B[i] = Bias + mats[i] * 128;
        GB.Y[i] = S + offs[i];
        GB.N[i] = ns[i];
        GB.YS[i] = strides[i];
        GB.tileStart[i] = tsum;
        tsum += (ns[i] + 127) / 128;
    }
    GB.tileStart[10] = tsum;
    GB.chunk = (tsum + NCTA_GEMM - 1) / NCTA_GEMM;
    GB.E = E;
    GB.cntI = I + ICNT_I;
    GB.cntU = I + ICNT_U;
    mma_gemm_batch<<<dim3(NCTA_GEMM, 2), 256, GEMM_SMEM>>>(GB);

    // 3) CSR: scan + scatter
    scan_kernel<<<2, 1024>>>(I + ICNT_I, I + ISTART_I, nItem,
                             I + ICNT_U, I + ISTART_U, nUser);
    scatter_kernel<<<(eTotal + 255) / 256, 256>>>(E, I + ISTART_I, I + ISTART_U,
                                                  I + ICNT_I, I + ICNT_U,
                                                  I + ICSR_I, I + ICSR_U);

    // 4) gather: softmax aggregate + GELU
    GatherIO G;
    G.Qi = S + OFF_Q_ITEM;
    G.Qu = S + OFF_Q_USER;
    G.KV[0] = S + OFF_KV_TASTE;
    G.KV[1] = S + OFF_KV_IMAGE;
    G.KV[2] = S + OFF_KV_USER;
    G.KV[3] = S + OFF_KV_ITEM;
    G.csrI = I + ICSR_I;   G.csrU = I + ICSR_U;
    G.startI = I + ISTART_I; G.startU = I + ISTART_U;
    G.gelI = S + OFF_GEL_ITEM; G.gelU = S + OFF_GEL_USER;
    G.prel = p_rel;
    G.nI = nItem; G.nU = nUser;
    int warps = nItem + nUser;
    gather_kernel<<<(warps + 7) / 8, 256>>>(G);

    // 5) fused output projections with sigmoid-gated residual
    float* out_i = (float*)d_out;
    float* out_u = (float*)d_out + (size_t)nItem * HID;
    OutBatch OB;
    OB.X[0] = S + OFF_GEL_ITEM; OB.X[1] = S + OFF_GEL_USER;
    OB.W[0] = Wfrag + 10ull * 16384; OB.W[1] = Wfrag + 11ull * 16384;
    OB.B[0] = Bias + 10 * 128; OB.B[1] = Bias + 11 * 128;
    OB.Y[0] = out_i; OB.Y[1] = out_u;
    OB.Res[0] = x_item; OB.Res[1] = x_user;
    OB.Skip = skip;
    OB.N[0] = nItem; OB.N[1] = nUser;
    int outTiles = ((nItem > nUser ? nItem : nUser) + 127) / 128;
    mma_gemm_out<<<dim3(outTiles, 2), 256, GEMM_SMEM>>>(OB);

    (void)n_in; (void)out_size;
}